// round 11
// baseline (speedup 1.0000x reference)
#include <cuda_runtime.h>
#include <cstdint>
#include <cstddef>
#include <math.h>

#define NN 100000
#define EE 1600000
#define SCAP 48          // staged edges per node (deg+1 <= SCAP); fallback beyond

// ---------------- scratch (device globals) -----------------------------------
__device__ __align__(16) float g_h[(size_t)NN * 128];     // GEMM output (per layer)
__device__ __align__(16) float g_out[(size_t)NN * 128];   // aggregation output
__device__ __align__(16) float g_agg[(size_t)NN * 16];    // layer-1 input-space aggregate
__device__ __align__(16) float g_als[NN * 4];
__device__ __align__(16) float g_ald[NN * 4];
__device__ double g_stats[256];
__device__ __align__(16) float g_scale[128];
__device__ __align__(16) float g_bias[128];
__device__ int g_done;
__device__ int g_cnt[NN];
__device__ int g_rowptr[NN + 1];
__device__ int g_pos[NN];
__device__ int g_col[EE];

// ---------------- helpers ----------------------------------------------------
__device__ __forceinline__ float lrelu(float x) { return x > 0.f ? x : 0.2f * x; }

__device__ __forceinline__ float4 lrelu4add(float4 a, float4 b) {
    return make_float4(lrelu(a.x + b.x), lrelu(a.y + b.y), lrelu(a.z + b.z), lrelu(a.w + b.w));
}
__device__ __forceinline__ void warpSum4(float4& s) {
#pragma unroll
    for (int off = 16; off >= 1; off >>= 1) {
        s.x += __shfl_xor_sync(0xffffffffu, s.x, off);
        s.y += __shfl_xor_sync(0xffffffffu, s.y, off);
        s.z += __shfl_xor_sync(0xffffffffu, s.z, off);
        s.w += __shfl_xor_sync(0xffffffffu, s.w, off);
    }
}

// Single-pass exp-weight staging (no max subtraction; logits are bounded:
// e = h.a_s + h.a_d with h pre-BN GEMM of normalized activations, |e| << 80).
// Stages (src, exp_weight4) into smem; outputs s4 = per-head exp-sum.
__device__ __forceinline__ bool weight_stage(
    int n, int start, int deg, float4 ald4, int lane,
    float4* sal, int* ssrc, float4& s4)
{
    bool fits = (deg < SCAP);
    s4 = make_float4(0.f, 0.f, 0.f, 0.f);
    for (int i = lane; i <= deg; i += 32) {
        int s = (i < deg) ? __ldg(&g_col[start + i]) : n;
        float4 a = *(const float4*)(g_als + (size_t)s * 4);
        float4 e = lrelu4add(a, ald4);
        float4 x = make_float4(__expf(e.x), __expf(e.y), __expf(e.z), __expf(e.w));
        s4.x += x.x; s4.y += x.y; s4.z += x.z; s4.w += x.w;
        if (fits) { sal[i] = x; ssrc[i] = s; }
    }
    warpSum4(s4);
    __syncwarp();
    return fits;
}

// ---------------- CSR build --------------------------------------------------
__global__ void zero_cnt_kernel() {
    int i = blockIdx.x * blockDim.x + threadIdx.x;
    if (i < NN) g_cnt[i] = 0;
}
__global__ void hist_kernel(const int* __restrict__ ei) {
    int i = blockIdx.x * blockDim.x + threadIdx.x;
    if (i < EE) atomicAdd(&g_cnt[ei[EE + i]], 1);
}
__global__ void scan_kernel() {
    __shared__ int sh[1024];
    const int T = 1024;
    const int per = (NN + T - 1) / T;
    int t = threadIdx.x;
    int begin = t * per;
    int end = begin + per; if (end > NN) end = NN;
    int sum = 0;
    for (int i = begin; i < end; i++) sum += g_cnt[i];
    sh[t] = sum;
    __syncthreads();
    for (int off = 1; off < T; off <<= 1) {
        int v = (t >= off) ? sh[t - off] : 0;
        __syncthreads();
        sh[t] += v;
        __syncthreads();
    }
    int run = (t == 0) ? 0 : sh[t - 1];
    for (int i = begin; i < end; i++) {
        int c = g_cnt[i];
        g_rowptr[i] = run;
        g_pos[i] = run;
        run += c;
    }
    if (t == T - 1) g_rowptr[NN] = run;
}
__global__ void scatter_kernel(const int* __restrict__ ei) {
    int i = blockIdx.x * blockDim.x + threadIdx.x;
    if (i >= EE) return;
    int d = ei[EE + i];
    int p = atomicAdd(&g_pos[d], 1);
    g_col[p] = ei[i];
}

// ---------------- BN stats + fused finalize (last-block pattern) -------------
// VEC=true: reads g_out rows (16B-aligned, stride == DOUT) with float4.
// VEC=false: scalar reads from xin with arbitrary stride (input x, stride 22).
template <int DOUT, bool VEC>
__global__ void stats_kernel(const float* __restrict__ xin, int stride,
                             const float* __restrict__ g, const float* __restrict__ be) {
    const float* in = xin ? xin : g_out;
    if (VEC) {
        constexpr int G = DOUT / 4;           // float4 groups per row
        constexpr int RPB = 128 / G;          // rows per block step
        int gi = threadIdx.x % G;
        int sub = threadIdx.x / G;
        int r = blockIdx.x * RPB + sub;
        int step = gridDim.x * RPB;
        float4 s = make_float4(0.f, 0.f, 0.f, 0.f);
        float4 q = make_float4(0.f, 0.f, 0.f, 0.f);
        for (; r < NN; r += step) {
            float4 v = *(const float4*)(in + (size_t)r * stride + gi * 4);
            s.x += v.x; s.y += v.y; s.z += v.z; s.w += v.w;
            q.x = fmaf(v.x, v.x, q.x); q.y = fmaf(v.y, v.y, q.y);
            q.z = fmaf(v.z, v.z, q.z); q.w = fmaf(v.w, v.w, q.w);
        }
        int f = gi * 4;
        atomicAdd(&g_stats[f + 0], (double)s.x);
        atomicAdd(&g_stats[f + 1], (double)s.y);
        atomicAdd(&g_stats[f + 2], (double)s.z);
        atomicAdd(&g_stats[f + 3], (double)s.w);
        atomicAdd(&g_stats[128 + f + 0], (double)q.x);
        atomicAdd(&g_stats[128 + f + 1], (double)q.y);
        atomicAdd(&g_stats[128 + f + 2], (double)q.z);
        atomicAdd(&g_stats[128 + f + 3], (double)q.w);
    } else {
        constexpr int RPB = 128 / DOUT;
        int f = threadIdx.x % DOUT;
        int sub = threadIdx.x / DOUT;
        int r = blockIdx.x * RPB + sub;
        int step = gridDim.x * RPB;
        float s = 0.f, q = 0.f;
        for (; r < NN; r += step) {
            float v = in[(size_t)r * stride + f];
            s += v;
            q = fmaf(v, v, q);
        }
        atomicAdd(&g_stats[f], (double)s);
        atomicAdd(&g_stats[128 + f], (double)q);
    }
    // ---- last block finalizes BN scale/bias ----
    __threadfence();
    __shared__ int lastb;
    if (threadIdx.x == 0)
        lastb = (atomicAdd(&g_done, 1) == (int)gridDim.x - 1) ? 1 : 0;
    __syncthreads();
    if (lastb) {
        int f = threadIdx.x;
        if (f < DOUT) {
            double mu = g_stats[f] / (double)NN;
            double var = g_stats[128 + f] / (double)NN - mu * mu;
            if (var < 0.0) var = 0.0;
            float sc = g[f] * rsqrtf((float)var + 1e-5f);
            g_scale[f] = sc;
            g_bias[f] = be[f] - (float)mu * sc;
            g_stats[f] = 0.0;
            g_stats[128 + f] = 0.0;
        }
        if (threadIdx.x == 0) g_done = 0;
    }
}

// ---------------- logits via va vectors (layer 1) ----------------------------
template <int DIN, int C, bool RELU>
__global__ void valogits_kernel(const float* __restrict__ xin, int istride,
                                const float* __restrict__ W,
                                const float* __restrict__ as,
                                const float* __restrict__ ad) {
    constexpr int DOUT = 4 * C;
    const float* in = xin ? xin : g_out;
    __shared__ float vas[4][DIN], vad[4][DIN];
    __shared__ float sc[DIN], sb[DIN];
    int tid = threadIdx.x;
    for (int e = tid; e < 8 * DIN; e += 256) {
        int which = e / (4 * DIN);
        int rem = e % (4 * DIN);
        int h = rem / DIN, k = rem % DIN;
        const float* av = which ? ad : as;
        float sum = 0.f;
        for (int c = 0; c < C; c++)
            sum = fmaf(W[k * DOUT + h * C + c], av[h * C + c], sum);
        if (which) vad[h][k] = sum; else vas[h][k] = sum;
    }
    if (tid < DIN) { sc[tid] = g_scale[tid]; sb[tid] = g_bias[tid]; }
    __syncthreads();
    int n = blockIdx.x * 256 + tid;
    if (n >= NN) return;
    float accs[4] = {0.f, 0.f, 0.f, 0.f};
    float accd[4] = {0.f, 0.f, 0.f, 0.f};
    const float* row = in + (size_t)n * istride;
#pragma unroll 4
    for (int k = 0; k < DIN; k++) {
        float a = fmaf(row[k], sc[k], sb[k]);
        if (RELU) a = fmaxf(a, 0.f);
#pragma unroll
        for (int h = 0; h < 4; h++) {
            accs[h] = fmaf(a, vas[h][k], accs[h]);
            accd[h] = fmaf(a, vad[h][k], accd[h]);
        }
    }
    *(float4*)(g_als + n * 4) = make_float4(accs[0], accs[1], accs[2], accs[3]);
    *(float4*)(g_ald + n * 4) = make_float4(accd[0], accd[1], accd[2], accd[3]);
}

// ---------------- layer-1 input-space aggregation (DIN=4, EPW=32) ------------
__global__ void __launch_bounds__(256) agg_in4_kernel(const float* __restrict__ x) {
    __shared__ float4 s_w[8][SCAP];
    __shared__ int    s_src[8][SCAP];
    int wib = threadIdx.x >> 5;
    int warp = (blockIdx.x * blockDim.x + threadIdx.x) >> 5;
    int lane = threadIdx.x & 31;
    if (warp >= NN) return;
    int n = warp;
    int start = g_rowptr[n];
    int deg = g_rowptr[n + 1] - start;
    float4 ald4 = *(const float4*)(g_ald + n * 4);

    float4 s4;
    bool fits = weight_stage(n, start, deg, ald4, lane,
                             &s_w[wib][0], &s_src[wib][0], s4);

    float4 sc4 = *(const float4*)(g_scale);
    float4 sb4 = *(const float4*)(g_bias);

    float4 acc0 = make_float4(0.f,0.f,0.f,0.f), acc1 = acc0, acc2 = acc0, acc3 = acc0;
    if (fits) {
#pragma unroll 2
        for (int i = lane; i <= deg; i += 32) {
            int s = s_src[wib][i];
            float4 w4 = s_w[wib][i];
            const float* p = x + (size_t)s * 22;
            float2 u0 = *(const float2*)p;
            float2 u1 = *(const float2*)(p + 2);
            float4 v = make_float4(fmaf(u0.x, sc4.x, sb4.x), fmaf(u0.y, sc4.y, sb4.y),
                                   fmaf(u1.x, sc4.z, sb4.z), fmaf(u1.y, sc4.w, sb4.w));
            acc0.x = fmaf(v.x, w4.x, acc0.x); acc0.y = fmaf(v.y, w4.x, acc0.y);
            acc0.z = fmaf(v.z, w4.x, acc0.z); acc0.w = fmaf(v.w, w4.x, acc0.w);
            acc1.x = fmaf(v.x, w4.y, acc1.x); acc1.y = fmaf(v.y, w4.y, acc1.y);
            acc1.z = fmaf(v.z, w4.y, acc1.z); acc1.w = fmaf(v.w, w4.y, acc1.w);
            acc2.x = fmaf(v.x, w4.z, acc2.x); acc2.y = fmaf(v.y, w4.z, acc2.y);
            acc2.z = fmaf(v.z, w4.z, acc2.z); acc2.w = fmaf(v.w, w4.z, acc2.w);
            acc3.x = fmaf(v.x, w4.w, acc3.x); acc3.y = fmaf(v.y, w4.w, acc3.y);
            acc3.z = fmaf(v.z, w4.w, acc3.z); acc3.w = fmaf(v.w, w4.w, acc3.w);
        }
    } else {
        for (int i = lane; i <= deg; i += 32) {
            int s = (i < deg) ? g_col[start + i] : n;
            float4 a = *(const float4*)(g_als + (size_t)s * 4);
            float4 e = lrelu4add(a, ald4);
            float4 w4 = make_float4(__expf(e.x), __expf(e.y), __expf(e.z), __expf(e.w));
            const float* p = x + (size_t)s * 22;
            float2 u0 = *(const float2*)p;
            float2 u1 = *(const float2*)(p + 2);
            float4 v = make_float4(fmaf(u0.x, sc4.x, sb4.x), fmaf(u0.y, sc4.y, sb4.y),
                                   fmaf(u1.x, sc4.z, sb4.z), fmaf(u1.y, sc4.w, sb4.w));
            acc0.x = fmaf(v.x, w4.x, acc0.x); acc0.y = fmaf(v.y, w4.x, acc0.y);
            acc0.z = fmaf(v.z, w4.x, acc0.z); acc0.w = fmaf(v.w, w4.x, acc0.w);
            acc1.x = fmaf(v.x, w4.y, acc1.x); acc1.y = fmaf(v.y, w4.y, acc1.y);
            acc1.z = fmaf(v.z, w4.y, acc1.z); acc1.w = fmaf(v.w, w4.y, acc1.w);
            acc2.x = fmaf(v.x, w4.z, acc2.x); acc2.y = fmaf(v.y, w4.z, acc2.y);
            acc2.z = fmaf(v.z, w4.z, acc2.z); acc2.w = fmaf(v.w, w4.z, acc2.w);
            acc3.x = fmaf(v.x, w4.w, acc3.x); acc3.y = fmaf(v.y, w4.w, acc3.y);
            acc3.z = fmaf(v.z, w4.w, acc3.z); acc3.w = fmaf(v.w, w4.w, acc3.w);
        }
    }
    warpSum4(acc0); warpSum4(acc1); warpSum4(acc2); warpSum4(acc3);
    if (lane == 0) {
        float4 inv = make_float4(1.f / (s4.x + 1e-16f), 1.f / (s4.y + 1e-16f),
                                 1.f / (s4.z + 1e-16f), 1.f / (s4.w + 1e-16f));
        acc0.x *= inv.x; acc0.y *= inv.x; acc0.z *= inv.x; acc0.w *= inv.x;
        acc1.x *= inv.y; acc1.y *= inv.y; acc1.z *= inv.y; acc1.w *= inv.y;
        acc2.x *= inv.z; acc2.y *= inv.z; acc2.z *= inv.z; acc2.w *= inv.z;
        acc3.x *= inv.w; acc3.y *= inv.w; acc3.z *= inv.w; acc3.w *= inv.w;
        float4* base = (float4*)(g_agg + (size_t)n * 16);
        base[0] = acc0; base[1] = acc1; base[2] = acc2; base[3] = acc3;
    }
}

// ---------------- layer-1 projection: out = blockdiag(W) @ agg ---------------
__global__ void __launch_bounds__(256) proj4_kernel(const float* __restrict__ W) {
    __shared__ float Ws[4 * 64];
    int tid = threadIdx.x;
    for (int i = tid; i < 4 * 64; i += 256) Ws[i] = W[i];
    __syncthreads();
    int n = blockIdx.x * 128 + tid / 2;
    int cg = tid % 2;
    if (n >= NN) return;
    int hb = cg * 2;
    float acc[32];
#pragma unroll
    for (int j = 0; j < 32; j++) acc[j] = 0.f;
    const float* ag = g_agg + (size_t)n * 16;
#pragma unroll
    for (int k = 0; k < 4; k++) {
        float a0 = ag[(hb + 0) * 4 + k];
        float a1 = ag[(hb + 1) * 4 + k];
#pragma unroll
        for (int c = 0; c < 16; c++) {
            acc[c]      = fmaf(a0, Ws[k * 64 + cg * 32 + c], acc[c]);
            acc[16 + c] = fmaf(a1, Ws[k * 64 + cg * 32 + 16 + c], acc[16 + c]);
        }
    }
    float4* op = (float4*)(g_out + (size_t)n * 64 + cg * 32);
#pragma unroll
    for (int q = 0; q < 8; q++)
        op[q] = make_float4(acc[4 * q], acc[4 * q + 1], acc[4 * q + 2], acc[4 * q + 3]);
}

// ---------------- GEMM + attention-logit epilogue (2 rows/thread) ------------
template <int DIN, int DOUT, bool RELU>
__global__ void __launch_bounds__(256) gemm_kernel(
                            const float* __restrict__ Wg,
                            const float* __restrict__ asg,
                            const float* __restrict__ adg) {
    const float* in = g_out;
    constexpr int R = DOUT / 32;          // threads per row-pair (each 32 cols)
    constexpr int ROWS = 2 * (256 / R);   // rows per block
    constexpr int C = DOUT / 4;
    constexpr int HPT = 32 / C;
    __shared__ float Ws[DIN * DOUT];
    __shared__ float as_sh[DOUT], ad_sh[DOUT];
    __shared__ float sc_sh[DIN], sb_sh[DIN];
    int tid = threadIdx.x;
    for (int i = tid; i < DIN * DOUT; i += 256) Ws[i] = Wg[i];
    if (tid < DOUT) { as_sh[tid] = asg[tid]; ad_sh[tid] = adg[tid]; }
    if (tid < DIN)  { sc_sh[tid] = g_scale[tid]; sb_sh[tid] = g_bias[tid]; }
    __syncthreads();
    int r0 = blockIdx.x * ROWS + 2 * (tid / R);
    int cg = tid % R;
    if (r0 >= NN) return;
    bool has1 = (r0 + 1 < NN);
    int r1 = has1 ? (r0 + 1) : r0;

    float acc0[32], acc1[32];
#pragma unroll
    for (int j = 0; j < 32; j++) { acc0[j] = 0.f; acc1[j] = 0.f; }
    const float* i0 = in + (size_t)r0 * DIN;
    const float* i1 = in + (size_t)r1 * DIN;
    const float* wp = Ws + cg * 32;
#pragma unroll 2
    for (int k4 = 0; k4 < DIN; k4 += 4) {
        float4 x0 = *(const float4*)(i0 + k4);
        float4 x1 = *(const float4*)(i1 + k4);
        float e0[4] = {x0.x, x0.y, x0.z, x0.w};
        float e1[4] = {x1.x, x1.y, x1.z, x1.w};
#pragma unroll
        for (int e = 0; e < 4; e++) {
            int k = k4 + e;
            float a0 = fmaf(e0[e], sc_sh[k], sb_sh[k]);
            float a1 = fmaf(e1[e], sc_sh[k], sb_sh[k]);
            if (RELU) { a0 = fmaxf(a0, 0.f); a1 = fmaxf(a1, 0.f); }
#pragma unroll
            for (int j = 0; j < 32; j++) {
                float w = wp[k * DOUT + j];
                acc0[j] = fmaf(a0, w, acc0[j]);
                acc1[j] = fmaf(a1, w, acc1[j]);
            }
        }
    }
    // store h rows
    float4* hp0 = (float4*)(g_h + (size_t)r0 * DOUT + cg * 32);
#pragma unroll
    for (int q = 0; q < 8; q++)
        hp0[q] = make_float4(acc0[4*q], acc0[4*q+1], acc0[4*q+2], acc0[4*q+3]);
    if (has1) {
        float4* hp1 = (float4*)(g_h + (size_t)r1 * DOUT + cg * 32);
#pragma unroll
        for (int q = 0; q < 8; q++)
            hp1[q] = make_float4(acc1[4*q], acc1[4*q+1], acc1[4*q+2], acc1[4*q+3]);
    }
    // logits
#pragma unroll
    for (int u = 0; u < HPT; u++) {
        float ss0 = 0.f, dd0 = 0.f, ss1 = 0.f, dd1 = 0.f;
#pragma unroll
        for (int j = 0; j < C; j++) {
            float aw = as_sh[cg * 32 + u * C + j];
            float dw = ad_sh[cg * 32 + u * C + j];
            ss0 = fmaf(acc0[u * C + j], aw, ss0);
            dd0 = fmaf(acc0[u * C + j], dw, dd0);
            ss1 = fmaf(acc1[u * C + j], aw, ss1);
            dd1 = fmaf(acc1[u * C + j], dw, dd1);
        }
        int head = (cg * 32) / C + u;
        g_als[r0 * 4 + head] = ss0;
        g_ald[r0 * 4 + head] = dd0;
        if (has1) {
            g_als[r1 * 4 + head] = ss1;
            g_ald[r1 * 4 + head] = dd1;
        }
    }
}

// ---------------- fused softmax + aggregation (templated VPT) ----------------
template <int DOUT, int VPT>
__global__ void __launch_bounds__(256) agg_node_kernel() {
    constexpr int C   = DOUT / 4;    // channels per head
    constexpr int LPE = DOUT / VPT;  // lanes per edge
    constexpr int EPW = 32 / LPE;    // edges in flight per warp
    constexpr int NV  = VPT / 4;     // float4 loads per lane per edge
    static_assert(VPT <= C, "lane channels must stay within one head");
    __shared__ float4 s_w[8][SCAP];
    __shared__ int    s_src[8][SCAP];
    int wib = threadIdx.x >> 5;
    int warp = (blockIdx.x * blockDim.x + threadIdx.x) >> 5;
    int lane = threadIdx.x & 31;
    if (warp >= NN) return;
    int n = warp;
    int start = g_rowptr[n];
    int deg = g_rowptr[n + 1] - start;
    float4 ald4 = *(const float4*)(g_ald + n * 4);

    float4 s4;
    bool fits = weight_stage(n, start, deg, ald4, lane,
                             &s_w[wib][0], &s_src[wib][0], s4);

    int cl = lane % LPE;            // channel block (VPT channels)
    int sg = lane / LPE;            // edge slot
    int head = (cl * VPT) / C;
    float sh   = (head == 0) ? s4.x : (head == 1) ? s4.y : (head == 2) ? s4.z : s4.w;
    float invh = 1.f / (sh + 1e-16f);

    float4 acc[NV];
#pragma unroll
    for (int v = 0; v < NV; v++) acc[v] = make_float4(0.f, 0.f, 0.f, 0.f);

    if (fits) {
        const float* swf = (const float*)&s_w[wib][0];
#pragma unroll 4
        for (int i = sg; i <= deg; i += EPW) {
            int s = s_src[wib][i];
            float w = swf[i * 4 + head];            // unnormalized weight
            const float4* hp = (const float4*)(g_h + (size_t)s * DOUT + cl * VPT);
#pragma unroll
            for (int v = 0; v < NV; v++) {
                float4 hv = hp[v];
                acc[v].x = fmaf(hv.x, w, acc[v].x);
                acc[v].y = fmaf(hv.y, w, acc[v].y);
                acc[v].z = fmaf(hv.z, w, acc[v].z);
                acc[v].w = fmaf(hv.w, w, acc[v].w);
            }
        }
    } else {
        float aldh = (head == 0) ? ald4.x : (head == 1) ? ald4.y : (head == 2) ? ald4.z : ald4.w;
        for (int i = sg; i <= deg; i += EPW) {
            int s = (i < deg) ? g_col[start + i] : n;
            float av = __ldg(&g_als[s * 4 + head]);
            float w = __expf(lrelu(av + aldh));
            const float4* hp = (const float4*)(g_h + (size_t)s * DOUT + cl * VPT);
#pragma unroll
            for (int v = 0; v < NV; v++) {
                float4 hv = hp[v];
                acc[v].x = fmaf(hv.x, w, acc[v].x);
                acc[v].y = fmaf(hv.y, w, acc[v].y);
                acc[v].z = fmaf(hv.z, w, acc[v].z);
                acc[v].w = fmaf(hv.w, w, acc[v].w);
            }
        }
    }
#pragma unroll
    for (int off = LPE; off < 32; off <<= 1) {
#pragma unroll
        for (int v = 0; v < NV; v++) {
            acc[v].x += __shfl_xor_sync(0xffffffffu, acc[v].x, off);
            acc[v].y += __shfl_xor_sync(0xffffffffu, acc[v].y, off);
            acc[v].z += __shfl_xor_sync(0xffffffffu, acc[v].z, off);
            acc[v].w += __shfl_xor_sync(0xffffffffu, acc[v].w, off);
        }
    }
    if (sg == 0) {
        float4* op = (float4*)(g_out + (size_t)n * DOUT + cl * VPT);
#pragma unroll
        for (int v = 0; v < NV; v++) {
            acc[v].x *= invh; acc[v].y *= invh; acc[v].z *= invh; acc[v].w *= invh;
            op[v] = acc[v];
        }
    }
}

// ---------------- final: bn+relu+linear(32->1) -------------------------------
__global__ void final_kernel(const float* __restrict__ ow, const float* __restrict__ ob,
                             float* __restrict__ out) {
    int n = blockIdx.x * blockDim.x + threadIdx.x;
    if (n >= NN) return;
    float acc = ob[0];
    const float* row = g_out + (size_t)n * 32;
#pragma unroll
    for (int k = 0; k < 32; k++) {
        float v = fmaxf(fmaf(row[k], g_scale[k], g_bias[k]), 0.f);
        acc = fmaf(v, ow[k], acc);
    }
    out[n] = acc;
}

// ---------------- launch ------------------------------------------------------
extern "C" void kernel_launch(void* const* d_in, const int* in_sizes, int n_in,
                              void* d_out, int out_size) {
    bool layB = (in_sizes[1] == 2 * EE);
    const float* x = (const float*)d_in[0];
    const int* ei = (const int*)d_in[layB ? 1 : (n_in - 1)];
    int base = layB ? 2 : 1;
    const float *W[4], *As[4], *Ad[4], *G[4], *Be[4];
    for (int l = 0; l < 4; l++) {
        int b = base + 6 * l;
        W[l]  = (const float*)d_in[b];
        As[l] = (const float*)d_in[b + 1];
        Ad[l] = (const float*)d_in[b + 2];
        G[l]  = (const float*)d_in[b + 4];
        Be[l] = (const float*)d_in[b + 5];
    }
    int tb = base + 24;
    const float* g0  = (const float*)d_in[tb];
    const float* be0 = (const float*)d_in[tb + 1];
    const float* ow  = (const float*)d_in[tb + 2];
    const float* ob  = (const float*)d_in[tb + 3];
    float* out = (float*)d_out;

    const int TPB = 256;
    int egrid = (EE + TPB - 1) / TPB;
    int wgrid = (NN * 32 + TPB - 1) / TPB;   // warp per node

    // CSR build (edges shared by all layers)
    zero_cnt_kernel<<<(NN + TPB - 1) / TPB, TPB>>>();
    hist_kernel<<<egrid, TPB>>>(ei);
    scan_kernel<<<1, 1024>>>();
    scatter_kernel<<<egrid, TPB>>>(ei);

    // input BN (x[:, :4], stride 22) — scalar path, fused bnfin
    stats_kernel<4, false><<<1024, 128>>>(x, 22, g0, be0);

    // layer 1: 4 -> 64 (input-space aggregation; EPW=32, 16B gathers)
    valogits_kernel<4, 16, false><<<(NN + 255) / 256, 256>>>(x, 22, W[0], As[0], Ad[0]);
    agg_in4_kernel<<<wgrid, TPB>>>(x);
    proj4_kernel<<<(NN + 127) / 128, 256>>>(W[0]);
    stats_kernel<64, true><<<1024, 128>>>(nullptr, 64, G[0], Be[0]);

    // layer 2: 64 -> 128
    gemm_kernel<64, 128, true><<<(NN + 127) / 128, 256>>>(W[1], As[1], Ad[1]);
    agg_node_kernel<128, 16><<<wgrid, TPB>>>();
    stats_kernel<128, true><<<1024, 128>>>(nullptr, 128, G[1], Be[1]);

    // layer 3: 128 -> 64
    gemm_kernel<128, 64, true><<<(NN + 255) / 256, 256>>>(W[2], As[2], Ad[2]);
    agg_node_kernel<64, 8><<<wgrid, TPB>>>();
    stats_kernel<64, true><<<1024, 128>>>(nullptr, 64, G[2], Be[2]);

    // layer 4: 64 -> 32
    gemm_kernel<64, 32, true><<<(NN + 511) / 512, 256>>>(W[3], As[3], Ad[3]);
    agg_node_kernel<32, 8><<<wgrid, TPB>>>();
    stats_kernel<32, true><<<1024, 128>>>(nullptr, 32, G[3], Be[3]);

    final_kernel<<<(NN + 255) / 256, 256>>>(ow, ob, out);
}

// round 12
// speedup vs baseline: 1.7516x; 1.7516x over previous
#include <cuda_runtime.h>
#include <cstdint>
#include <cstddef>
#include <math.h>

#define NN 100000
#define EE 1600000
#define SCAP 48          // staged edges per node (deg+1 <= SCAP); fallback beyond

// ---------------- scratch (device globals) -----------------------------------
__device__ __align__(16) float g_h[(size_t)NN * 128];     // GEMM output (per layer)
__device__ __align__(16) float g_out[(size_t)NN * 128];   // aggregation output
__device__ __align__(16) float g_agg[(size_t)NN * 16];    // layer-1 input-space aggregate
__device__ __align__(16) float g_als[NN * 4];
__device__ __align__(16) float g_ald[NN * 4];
__device__ double g_stats[256];
__device__ __align__(16) float g_scale[128];
__device__ __align__(16) float g_bias[128];
__device__ int g_cnt[NN];
__device__ int g_rowptr[NN + 1];
__device__ int g_pos[NN];
__device__ int g_col[EE];

// ---------------- helpers ----------------------------------------------------
__device__ __forceinline__ float lrelu(float x) { return x > 0.f ? x : 0.2f * x; }

__device__ __forceinline__ float4 lrelu4add(float4 a, float4 b) {
    return make_float4(lrelu(a.x + b.x), lrelu(a.y + b.y), lrelu(a.z + b.z), lrelu(a.w + b.w));
}
__device__ __forceinline__ void warpSum4(float4& s) {
#pragma unroll
    for (int off = 16; off >= 1; off >>= 1) {
        s.x += __shfl_xor_sync(0xffffffffu, s.x, off);
        s.y += __shfl_xor_sync(0xffffffffu, s.y, off);
        s.z += __shfl_xor_sync(0xffffffffu, s.z, off);
        s.w += __shfl_xor_sync(0xffffffffu, s.w, off);
    }
}

// Single-pass exp-weight staging (no max subtraction; logits are bounded:
// e = h.a_s + h.a_d with h pre-BN GEMM of normalized activations, |e| << 80).
// Stages (src, exp_weight4) into smem; outputs s4 = per-head exp-sum.
__device__ __forceinline__ bool weight_stage(
    int n, int start, int deg, float4 ald4, int lane,
    float4* sal, int* ssrc, float4& s4)
{
    bool fits = (deg < SCAP);
    s4 = make_float4(0.f, 0.f, 0.f, 0.f);
    for (int i = lane; i <= deg; i += 32) {
        int s = (i < deg) ? __ldg(&g_col[start + i]) : n;
        float4 a = *(const float4*)(g_als + (size_t)s * 4);
        float4 e = lrelu4add(a, ald4);
        float4 x = make_float4(__expf(e.x), __expf(e.y), __expf(e.z), __expf(e.w));
        s4.x += x.x; s4.y += x.y; s4.z += x.z; s4.w += x.w;
        if (fits) { sal[i] = x; ssrc[i] = s; }
    }
    warpSum4(s4);
    __syncwarp();
    return fits;
}

// ---------------- CSR build --------------------------------------------------
__global__ void zero_cnt_kernel() {
    int i = blockIdx.x * blockDim.x + threadIdx.x;
    if (i < NN) g_cnt[i] = 0;
}
__global__ void hist_kernel(const int* __restrict__ ei) {
    int i = blockIdx.x * blockDim.x + threadIdx.x;
    if (i < EE) atomicAdd(&g_cnt[ei[EE + i]], 1);
}
__global__ void scan_kernel() {
    __shared__ int sh[1024];
    const int T = 1024;
    const int per = (NN + T - 1) / T;
    int t = threadIdx.x;
    int begin = t * per;
    int end = begin + per; if (end > NN) end = NN;
    int sum = 0;
    for (int i = begin; i < end; i++) sum += g_cnt[i];
    sh[t] = sum;
    __syncthreads();
    for (int off = 1; off < T; off <<= 1) {
        int v = (t >= off) ? sh[t - off] : 0;
        __syncthreads();
        sh[t] += v;
        __syncthreads();
    }
    int run = (t == 0) ? 0 : sh[t - 1];
    for (int i = begin; i < end; i++) {
        int c = g_cnt[i];
        g_rowptr[i] = run;
        g_pos[i] = run;
        run += c;
    }
    if (t == T - 1) g_rowptr[NN] = run;
}
__global__ void scatter_kernel(const int* __restrict__ ei) {
    int i = blockIdx.x * blockDim.x + threadIdx.x;
    if (i >= EE) return;
    int d = ei[EE + i];
    int p = atomicAdd(&g_pos[d], 1);
    g_col[p] = ei[i];
}

// ---------------- BN stats ---------------------------------------------------
template <int DOUT>
__global__ void stats_kernel(const float* __restrict__ xin, int stride) {
    const float* in = xin ? xin : g_out;
    constexpr int RPB = 128 / DOUT;
    int f = threadIdx.x % DOUT;
    int sub = threadIdx.x / DOUT;
    int r = blockIdx.x * RPB + sub;
    int step = gridDim.x * RPB;
    float s = 0.f, q = 0.f;
    for (; r < NN; r += step) {
        float v = in[(size_t)r * stride + f];
        s += v;
        q = fmaf(v, v, q);
    }
    atomicAdd(&g_stats[f], (double)s);
    atomicAdd(&g_stats[128 + f], (double)q);
}

template <int DOUT>
__global__ void bnfin_kernel(const float* __restrict__ g, const float* __restrict__ be) {
    int f = threadIdx.x;
    if (f >= DOUT) return;
    double mu = g_stats[f] / (double)NN;
    double var = g_stats[128 + f] / (double)NN - mu * mu;
    if (var < 0.0) var = 0.0;
    float sc = g[f] * rsqrtf((float)var + 1e-5f);
    g_scale[f] = sc;
    g_bias[f] = be[f] - (float)mu * sc;
    g_stats[f] = 0.0;
    g_stats[128 + f] = 0.0;
}

// ---------------- logits via va vectors (layer 1) ----------------------------
template <int DIN, int C, bool RELU>
__global__ void valogits_kernel(const float* __restrict__ xin, int istride,
                                const float* __restrict__ W,
                                const float* __restrict__ as,
                                const float* __restrict__ ad) {
    constexpr int DOUT = 4 * C;
    const float* in = xin ? xin : g_out;
    __shared__ float vas[4][DIN], vad[4][DIN];
    __shared__ float sc[DIN], sb[DIN];
    int tid = threadIdx.x;
    for (int e = tid; e < 8 * DIN; e += 256) {
        int which = e / (4 * DIN);
        int rem = e % (4 * DIN);
        int h = rem / DIN, k = rem % DIN;
        const float* av = which ? ad : as;
        float sum = 0.f;
        for (int c = 0; c < C; c++)
            sum = fmaf(W[k * DOUT + h * C + c], av[h * C + c], sum);
        if (which) vad[h][k] = sum; else vas[h][k] = sum;
    }
    if (tid < DIN) { sc[tid] = g_scale[tid]; sb[tid] = g_bias[tid]; }
    __syncthreads();
    int n = blockIdx.x * 256 + tid;
    if (n >= NN) return;
    float accs[4] = {0.f, 0.f, 0.f, 0.f};
    float accd[4] = {0.f, 0.f, 0.f, 0.f};
    const float* row = in + (size_t)n * istride;
#pragma unroll 4
    for (int k = 0; k < DIN; k++) {
        float a = fmaf(row[k], sc[k], sb[k]);
        if (RELU) a = fmaxf(a, 0.f);
#pragma unroll
        for (int h = 0; h < 4; h++) {
            accs[h] = fmaf(a, vas[h][k], accs[h]);
            accd[h] = fmaf(a, vad[h][k], accd[h]);
        }
    }
    *(float4*)(g_als + n * 4) = make_float4(accs[0], accs[1], accs[2], accs[3]);
    *(float4*)(g_ald + n * 4) = make_float4(accd[0], accd[1], accd[2], accd[3]);
}

// ---------------- layer-1 input-space aggregation (DIN=4, EPW=32) ------------
__global__ void __launch_bounds__(256) agg_in4_kernel(const float* __restrict__ x) {
    __shared__ float4 s_w[8][SCAP];
    __shared__ int    s_src[8][SCAP];
    int wib = threadIdx.x >> 5;
    int warp = (blockIdx.x * blockDim.x + threadIdx.x) >> 5;
    int lane = threadIdx.x & 31;
    if (warp >= NN) return;
    int n = warp;
    int start = g_rowptr[n];
    int deg = g_rowptr[n + 1] - start;
    float4 ald4 = *(const float4*)(g_ald + n * 4);

    float4 s4;
    bool fits = weight_stage(n, start, deg, ald4, lane,
                             &s_w[wib][0], &s_src[wib][0], s4);

    float4 sc4 = *(const float4*)(g_scale);
    float4 sb4 = *(const float4*)(g_bias);

    float4 acc0 = make_float4(0.f,0.f,0.f,0.f), acc1 = acc0, acc2 = acc0, acc3 = acc0;
    if (fits) {
#pragma unroll 2
        for (int i = lane; i <= deg; i += 32) {
            int s = s_src[wib][i];
            float4 w4 = s_w[wib][i];
            const float* p = x + (size_t)s * 22;
            float2 u0 = *(const float2*)p;
            float2 u1 = *(const float2*)(p + 2);
            float4 v = make_float4(fmaf(u0.x, sc4.x, sb4.x), fmaf(u0.y, sc4.y, sb4.y),
                                   fmaf(u1.x, sc4.z, sb4.z), fmaf(u1.y, sc4.w, sb4.w));
            acc0.x = fmaf(v.x, w4.x, acc0.x); acc0.y = fmaf(v.y, w4.x, acc0.y);
            acc0.z = fmaf(v.z, w4.x, acc0.z); acc0.w = fmaf(v.w, w4.x, acc0.w);
            acc1.x = fmaf(v.x, w4.y, acc1.x); acc1.y = fmaf(v.y, w4.y, acc1.y);
            acc1.z = fmaf(v.z, w4.y, acc1.z); acc1.w = fmaf(v.w, w4.y, acc1.w);
            acc2.x = fmaf(v.x, w4.z, acc2.x); acc2.y = fmaf(v.y, w4.z, acc2.y);
            acc2.z = fmaf(v.z, w4.z, acc2.z); acc2.w = fmaf(v.w, w4.z, acc2.w);
            acc3.x = fmaf(v.x, w4.w, acc3.x); acc3.y = fmaf(v.y, w4.w, acc3.y);
            acc3.z = fmaf(v.z, w4.w, acc3.z); acc3.w = fmaf(v.w, w4.w, acc3.w);
        }
    } else {
        for (int i = lane; i <= deg; i += 32) {
            int s = (i < deg) ? g_col[start + i] : n;
            float4 a = *(const float4*)(g_als + (size_t)s * 4);
            float4 e = lrelu4add(a, ald4);
            float4 w4 = make_float4(__expf(e.x), __expf(e.y), __expf(e.z), __expf(e.w));
            const float* p = x + (size_t)s * 22;
            float2 u0 = *(const float2*)p;
            float2 u1 = *(const float2*)(p + 2);
            float4 v = make_float4(fmaf(u0.x, sc4.x, sb4.x), fmaf(u0.y, sc4.y, sb4.y),
                                   fmaf(u1.x, sc4.z, sb4.z), fmaf(u1.y, sc4.w, sb4.w));
            acc0.x = fmaf(v.x, w4.x, acc0.x); acc0.y = fmaf(v.y, w4.x, acc0.y);
            acc0.z = fmaf(v.z, w4.x, acc0.z); acc0.w = fmaf(v.w, w4.x, acc0.w);
            acc1.x = fmaf(v.x, w4.y, acc1.x); acc1.y = fmaf(v.y, w4.y, acc1.y);
            acc1.z = fmaf(v.z, w4.y, acc1.z); acc1.w = fmaf(v.w, w4.y, acc1.w);
            acc2.x = fmaf(v.x, w4.z, acc2.x); acc2.y = fmaf(v.y, w4.z, acc2.y);
            acc2.z = fmaf(v.z, w4.z, acc2.z); acc2.w = fmaf(v.w, w4.z, acc2.w);
            acc3.x = fmaf(v.x, w4.w, acc3.x); acc3.y = fmaf(v.y, w4.w, acc3.y);
            acc3.z = fmaf(v.z, w4.w, acc3.z); acc3.w = fmaf(v.w, w4.w, acc3.w);
        }
    }
    warpSum4(acc0); warpSum4(acc1); warpSum4(acc2); warpSum4(acc3);
    if (lane == 0) {
        float4 inv = make_float4(1.f / (s4.x + 1e-16f), 1.f / (s4.y + 1e-16f),
                                 1.f / (s4.z + 1e-16f), 1.f / (s4.w + 1e-16f));
        acc0.x *= inv.x; acc0.y *= inv.x; acc0.z *= inv.x; acc0.w *= inv.x;
        acc1.x *= inv.y; acc1.y *= inv.y; acc1.z *= inv.y; acc1.w *= inv.y;
        acc2.x *= inv.z; acc2.y *= inv.z; acc2.z *= inv.z; acc2.w *= inv.z;
        acc3.x *= inv.w; acc3.y *= inv.w; acc3.z *= inv.w; acc3.w *= inv.w;
        float4* base = (float4*)(g_agg + (size_t)n * 16);
        base[0] = acc0; base[1] = acc1; base[2] = acc2; base[3] = acc3;
    }
}

// ---------------- layer-1 projection: out = blockdiag(W) @ agg ---------------
__global__ void __launch_bounds__(256) proj4_kernel(const float* __restrict__ W) {
    __shared__ float Ws[4 * 64];
    int tid = threadIdx.x;
    for (int i = tid; i < 4 * 64; i += 256) Ws[i] = W[i];
    __syncthreads();
    int n = blockIdx.x * 128 + tid / 2;
    int cg = tid % 2;
    if (n >= NN) return;
    int hb = cg * 2;
    float acc[32];
#pragma unroll
    for (int j = 0; j < 32; j++) acc[j] = 0.f;
    const float* ag = g_agg + (size_t)n * 16;
#pragma unroll
    for (int k = 0; k < 4; k++) {
        float a0 = ag[(hb + 0) * 4 + k];
        float a1 = ag[(hb + 1) * 4 + k];
#pragma unroll
        for (int c = 0; c < 16; c++) {
            acc[c]      = fmaf(a0, Ws[k * 64 + cg * 32 + c], acc[c]);
            acc[16 + c] = fmaf(a1, Ws[k * 64 + cg * 32 + 16 + c], acc[16 + c]);
        }
    }
    float4* op = (float4*)(g_out + (size_t)n * 64 + cg * 32);
#pragma unroll
    for (int q = 0; q < 8; q++)
        op[q] = make_float4(acc[4 * q], acc[4 * q + 1], acc[4 * q + 2], acc[4 * q + 3]);
}

// ---------------- GEMM + attention-logit epilogue (2 rows/thread) ------------
template <int DIN, int DOUT, bool RELU>
__global__ void __launch_bounds__(256) gemm_kernel(
                            const float* __restrict__ Wg,
                            const float* __restrict__ asg,
                            const float* __restrict__ adg) {
    const float* in = g_out;
    constexpr int R = DOUT / 32;          // threads per row-pair (each 32 cols)
    constexpr int ROWS = 2 * (256 / R);   // rows per block
    constexpr int C = DOUT / 4;
    constexpr int HPT = 32 / C;
    __shared__ float Ws[DIN * DOUT];
    __shared__ float as_sh[DOUT], ad_sh[DOUT];
    __shared__ float sc_sh[DIN], sb_sh[DIN];
    int tid = threadIdx.x;
    for (int i = tid; i < DIN * DOUT; i += 256) Ws[i] = Wg[i];
    if (tid < DOUT) { as_sh[tid] = asg[tid]; ad_sh[tid] = adg[tid]; }
    if (tid < DIN)  { sc_sh[tid] = g_scale[tid]; sb_sh[tid] = g_bias[tid]; }
    __syncthreads();
    int r0 = blockIdx.x * ROWS + 2 * (tid / R);
    int cg = tid % R;
    if (r0 >= NN) return;
    bool has1 = (r0 + 1 < NN);
    int r1 = has1 ? (r0 + 1) : r0;

    float acc0[32], acc1[32];
#pragma unroll
    for (int j = 0; j < 32; j++) { acc0[j] = 0.f; acc1[j] = 0.f; }
    const float* i0 = in + (size_t)r0 * DIN;
    const float* i1 = in + (size_t)r1 * DIN;
    const float* wp = Ws + cg * 32;
#pragma unroll 2
    for (int k = 0; k < DIN; k++) {
        float a0 = fmaf(i0[k], sc_sh[k], sb_sh[k]);
        float a1 = fmaf(i1[k], sc_sh[k], sb_sh[k]);
        if (RELU) { a0 = fmaxf(a0, 0.f); a1 = fmaxf(a1, 0.f); }
#pragma unroll
        for (int j = 0; j < 32; j++) {
            float w = wp[k * DOUT + j];
            acc0[j] = fmaf(a0, w, acc0[j]);
            acc1[j] = fmaf(a1, w, acc1[j]);
        }
    }
    // store h rows
    float4* hp0 = (float4*)(g_h + (size_t)r0 * DOUT + cg * 32);
#pragma unroll
    for (int q = 0; q < 8; q++)
        hp0[q] = make_float4(acc0[4*q], acc0[4*q+1], acc0[4*q+2], acc0[4*q+3]);
    if (has1) {
        float4* hp1 = (float4*)(g_h + (size_t)r1 * DOUT + cg * 32);
#pragma unroll
        for (int q = 0; q < 8; q++)
            hp1[q] = make_float4(acc1[4*q], acc1[4*q+1], acc1[4*q+2], acc1[4*q+3]);
    }
    // logits
#pragma unroll
    for (int u = 0; u < HPT; u++) {
        float ss0 = 0.f, dd0 = 0.f, ss1 = 0.f, dd1 = 0.f;
#pragma unroll
        for (int j = 0; j < C; j++) {
            float aw = as_sh[cg * 32 + u * C + j];
            float dw = ad_sh[cg * 32 + u * C + j];
            ss0 = fmaf(acc0[u * C + j], aw, ss0);
            dd0 = fmaf(acc0[u * C + j], dw, dd0);
            ss1 = fmaf(acc1[u * C + j], aw, ss1);
            dd1 = fmaf(acc1[u * C + j], dw, dd1);
        }
        int head = (cg * 32) / C + u;
        g_als[r0 * 4 + head] = ss0;
        g_ald[r0 * 4 + head] = dd0;
        if (has1) {
            g_als[r1 * 4 + head] = ss1;
            g_ald[r1 * 4 + head] = dd1;
        }
    }
}

// ---------------- fused softmax + aggregation (templated VPT) ----------------
template <int DOUT, int VPT>
__global__ void __launch_bounds__(256) agg_node_kernel() {
    constexpr int C   = DOUT / 4;    // channels per head
    constexpr int LPE = DOUT / VPT;  // lanes per edge
    constexpr int EPW = 32 / LPE;    // edges in flight per warp
    constexpr int NV  = VPT / 4;     // float4 loads per lane per edge
    static_assert(VPT <= C, "lane channels must stay within one head");
    __shared__ float4 s_w[8][SCAP];
    __shared__ int    s_src[8][SCAP];
    int wib = threadIdx.x >> 5;
    int warp = (blockIdx.x * blockDim.x + threadIdx.x) >> 5;
    int lane = threadIdx.x & 31;
    if (warp >= NN) return;
    int n = warp;
    int start = g_rowptr[n];
    int deg = g_rowptr[n + 1] - start;
    float4 ald4 = *(const float4*)(g_ald + n * 4);

    float4 s4;
    bool fits = weight_stage(n, start, deg, ald4, lane,
                             &s_w[wib][0], &s_src[wib][0], s4);

    int cl = lane % LPE;            // channel block (VPT channels)
    int sg = lane / LPE;            // edge slot
    int head = (cl * VPT) / C;
    float sh   = (head == 0) ? s4.x : (head == 1) ? s4.y : (head == 2) ? s4.z : s4.w;
    float invh = 1.f / (sh + 1e-16f);

    float4 acc[NV];
#pragma unroll
    for (int v = 0; v < NV; v++) acc[v] = make_float4(0.f, 0.f, 0.f, 0.f);

    if (fits) {
        const float* swf = (const float*)&s_w[wib][0];
#pragma unroll 4
        for (int i = sg; i <= deg; i += EPW) {
            int s = s_src[wib][i];
            float w = swf[i * 4 + head];            // unnormalized weight
            const float4* hp = (const float4*)(g_h + (size_t)s * DOUT + cl * VPT);
#pragma unroll
            for (int v = 0; v < NV; v++) {
                float4 hv = hp[v];
                acc[v].x = fmaf(hv.x, w, acc[v].x);
                acc[v].y = fmaf(hv.y, w, acc[v].y);
                acc[v].z = fmaf(hv.z, w, acc[v].z);
                acc[v].w = fmaf(hv.w, w, acc[v].w);
            }
        }
    } else {
        float aldh = (head == 0) ? ald4.x : (head == 1) ? ald4.y : (head == 2) ? ald4.z : ald4.w;
        for (int i = sg; i <= deg; i += EPW) {
            int s = (i < deg) ? g_col[start + i] : n;
            float av = __ldg(&g_als[s * 4 + head]);
            float w = __expf(lrelu(av + aldh));
            const float4* hp = (const float4*)(g_h + (size_t)s * DOUT + cl * VPT);
#pragma unroll
            for (int v = 0; v < NV; v++) {
                float4 hv = hp[v];
                acc[v].x = fmaf(hv.x, w, acc[v].x);
                acc[v].y = fmaf(hv.y, w, acc[v].y);
                acc[v].z = fmaf(hv.z, w, acc[v].z);
                acc[v].w = fmaf(hv.w, w, acc[v].w);
            }
        }
    }
#pragma unroll
    for (int off = LPE; off < 32; off <<= 1) {
#pragma unroll
        for (int v = 0; v < NV; v++) {
            acc[v].x += __shfl_xor_sync(0xffffffffu, acc[v].x, off);
            acc[v].y += __shfl_xor_sync(0xffffffffu, acc[v].y, off);
            acc[v].z += __shfl_xor_sync(0xffffffffu, acc[v].z, off);
            acc[v].w += __shfl_xor_sync(0xffffffffu, acc[v].w, off);
        }
    }
    if (sg == 0) {
        float4* op = (float4*)(g_out + (size_t)n * DOUT + cl * VPT);
#pragma unroll
        for (int v = 0; v < NV; v++) {
            acc[v].x *= invh; acc[v].y *= invh; acc[v].z *= invh; acc[v].w *= invh;
            op[v] = acc[v];
        }
    }
}

// ---------------- final: bn+relu+linear(32->1) -------------------------------
__global__ void final_kernel(const float* __restrict__ ow, const float* __restrict__ ob,
                             float* __restrict__ out) {
    int n = blockIdx.x * blockDim.x + threadIdx.x;
    if (n >= NN) return;
    float acc = ob[0];
    const float4* row = (const float4*)(g_out + (size_t)n * 32);
#pragma unroll
    for (int q = 0; q < 8; q++) {
        float4 v = row[q];
        int k = 4 * q;
        float v0 = fmaxf(fmaf(v.x, g_scale[k + 0], g_bias[k + 0]), 0.f);
        float v1 = fmaxf(fmaf(v.y, g_scale[k + 1], g_bias[k + 1]), 0.f);
        float v2 = fmaxf(fmaf(v.z, g_scale[k + 2], g_bias[k + 2]), 0.f);
        float v3 = fmaxf(fmaf(v.w, g_scale[k + 3], g_bias[k + 3]), 0.f);
        acc = fmaf(v0, ow[k + 0], acc);
        acc = fmaf(v1, ow[k + 1], acc);
        acc = fmaf(v2, ow[k + 2], acc);
        acc = fmaf(v3, ow[k + 3], acc);
    }
    out[n] = acc;
}

// ---------------- launch ------------------------------------------------------
extern "C" void kernel_launch(void* const* d_in, const int* in_sizes, int n_in,
                              void* d_out, int out_size) {
    bool layB = (in_sizes[1] == 2 * EE);
    const float* x = (const float*)d_in[0];
    const int* ei = (const int*)d_in[layB ? 1 : (n_in - 1)];
    int base = layB ? 2 : 1;
    const float *W[4], *As[4], *Ad[4], *G[4], *Be[4];
    for (int l = 0; l < 4; l++) {
        int b = base + 6 * l;
        W[l]  = (const float*)d_in[b];
        As[l] = (const float*)d_in[b + 1];
        Ad[l] = (const float*)d_in[b + 2];
        G[l]  = (const float*)d_in[b + 4];
        Be[l] = (const float*)d_in[b + 5];
    }
    int tb = base + 24;
    const float* g0  = (const float*)d_in[tb];
    const float* be0 = (const float*)d_in[tb + 1];
    const float* ow  = (const float*)d_in[tb + 2];
    const float* ob  = (const float*)d_in[tb + 3];
    float* out = (float*)d_out;

    const int TPB = 256;
    int egrid = (EE + TPB - 1) / TPB;
    int wgrid = (NN * 32 + TPB - 1) / TPB;   // warp per node

    // CSR build (edges shared by all layers)
    zero_cnt_kernel<<<(NN + TPB - 1) / TPB, TPB>>>();
    hist_kernel<<<egrid, TPB>>>(ei);
    scan_kernel<<<1, 1024>>>();
    scatter_kernel<<<egrid, TPB>>>(ei);

    // input BN (x[:, :4], stride 22)
    stats_kernel<4><<<1024, 128>>>(x, 22);
    bnfin_kernel<4><<<1, 4>>>(g0, be0);

    // layer 1: 4 -> 64 (input-space aggregation; EPW=32, 16B gathers)
    valogits_kernel<4, 16, false><<<(NN + 255) / 256, 256>>>(x, 22, W[0], As[0], Ad[0]);
    agg_in4_kernel<<<wgrid, TPB>>>(x);
    proj4_kernel<<<(NN + 127) / 128, 256>>>(W[0]);
    stats_kernel<64><<<1024, 128>>>(nullptr, 64);
    bnfin_kernel<64><<<1, 64>>>(G[0], Be[0]);

    // layer 2: 64 -> 128
    gemm_kernel<64, 128, true><<<(NN + 127) / 128, 256>>>(W[1], As[1], Ad[1]);
    agg_node_kernel<128, 16><<<wgrid, TPB>>>();
    stats_kernel<128><<<1024, 128>>>(nullptr, 128);
    bnfin_kernel<128><<<1, 128>>>(G[1], Be[1]);

    // layer 3: 128 -> 64
    gemm_kernel<128, 64, true><<<(NN + 255) / 256, 256>>>(W[2], As[2], Ad[2]);
    agg_node_kernel<64, 8><<<wgrid, TPB>>>();
    stats_kernel<64><<<1024, 128>>>(nullptr, 64);
    bnfin_kernel<64><<<1, 64>>>(G[2], Be[2]);

    // layer 4: 64 -> 32
    gemm_kernel<64, 32, true><<<(NN + 511) / 512, 256>>>(W[3], As[3], Ad[3]);
    agg_node_kernel<32, 8><<<wgrid, TPB>>>();
    stats_kernel<32><<<1024, 128>>>(nullptr, 32);
    bnfin_kernel<32><<<1, 32>>>(G[3], Be[3]);

    final_kernel<<<(NN + 255) / 256, 256>>>(ow, ob, out);
}

// round 13
// speedup vs baseline: 1.7814x; 1.0170x over previous
#include <cuda_runtime.h>
#include <cstdint>
#include <cstddef>
#include <math.h>

#define NN 100000
#define EE 1600000
#define SCAP 48          // staged edges per node (deg+1 <= SCAP); fallback beyond

// ---------------- scratch (device globals) -----------------------------------
__device__ __align__(16) float g_h[(size_t)NN * 128];     // GEMM output (per layer)
__device__ __align__(16) float g_out[(size_t)NN * 128];   // aggregation output
__device__ __align__(16) float g_als[NN * 4];
__device__ __align__(16) float g_ald[NN * 4];
__device__ double g_stats[5 * 256];                       // 5 BN slots: [f]=sum,[128+f]=sumsq
__device__ int g_cnt[NN];
__device__ int g_rowptr[NN + 1];
__device__ int g_pos[NN];
__device__ int g_col[EE];

// ---------------- helpers ----------------------------------------------------
__device__ __forceinline__ float lrelu(float x) { return x > 0.f ? x : 0.2f * x; }

__device__ __forceinline__ float4 lrelu4add(float4 a, float4 b) {
    return make_float4(lrelu(a.x + b.x), lrelu(a.y + b.y), lrelu(a.z + b.z), lrelu(a.w + b.w));
}
__device__ __forceinline__ void warpSum4(float4& s) {
#pragma unroll
    for (int off = 16; off >= 1; off >>= 1) {
        s.x += __shfl_xor_sync(0xffffffffu, s.x, off);
        s.y += __shfl_xor_sync(0xffffffffu, s.y, off);
        s.z += __shfl_xor_sync(0xffffffffu, s.z, off);
        s.w += __shfl_xor_sync(0xffffffffu, s.w, off);
    }
}

// Per-block BN scale/bias from stats slot (deterministic; identical in all blocks).
__device__ __forceinline__ void bn_from_stats(int f, int slot,
                                              const float* g, const float* be,
                                              float* sc_sh, float* sb_sh) {
    const double* st = g_stats + slot * 256;
    double mu = st[f] / (double)NN;
    double var = st[128 + f] / (double)NN - mu * mu;
    if (var < 0.0) var = 0.0;
    float sc = g[f] * rsqrtf((float)var + 1e-5f);
    sc_sh[f] = sc;
    sb_sh[f] = be[f] - (float)mu * sc;
}

// Single-pass exp-weight staging (no max subtraction; logits bounded).
// Stages (src, exp_weight4) into smem; outputs s4 = per-head exp-sum (all lanes).
__device__ __forceinline__ bool weight_stage(
    int n, int start, int deg, float4 ald4, int lane,
    float4* sal, int* ssrc, float4& s4)
{
    bool fits = (deg < SCAP);
    s4 = make_float4(0.f, 0.f, 0.f, 0.f);
    for (int i = lane; i <= deg; i += 32) {
        int s = (i < deg) ? __ldg(&g_col[start + i]) : n;
        float4 a = *(const float4*)(g_als + (size_t)s * 4);
        float4 e = lrelu4add(a, ald4);
        float4 x = make_float4(__expf(e.x), __expf(e.y), __expf(e.z), __expf(e.w));
        s4.x += x.x; s4.y += x.y; s4.z += x.z; s4.w += x.w;
        if (fits) { sal[i] = x; ssrc[i] = s; }
    }
    warpSum4(s4);
    __syncwarp();
    return fits;
}

// ---------------- CSR build + stats zero -------------------------------------
__global__ void zero_cnt_kernel() {
    int i = blockIdx.x * blockDim.x + threadIdx.x;
    if (i < NN) g_cnt[i] = 0;
    if (i < 5 * 256) g_stats[i] = 0.0;
}
__global__ void hist_kernel(const int* __restrict__ ei) {
    int i = blockIdx.x * blockDim.x + threadIdx.x;
    if (i < EE) atomicAdd(&g_cnt[ei[EE + i]], 1);
}
__global__ void scan_kernel() {
    __shared__ int sh[1024];
    const int T = 1024;
    const int per = (NN + T - 1) / T;
    int t = threadIdx.x;
    int begin = t * per;
    int end = begin + per; if (end > NN) end = NN;
    int sum = 0;
    for (int i = begin; i < end; i++) sum += g_cnt[i];
    sh[t] = sum;
    __syncthreads();
    for (int off = 1; off < T; off <<= 1) {
        int v = (t >= off) ? sh[t - off] : 0;
        __syncthreads();
        sh[t] += v;
        __syncthreads();
    }
    int run = (t == 0) ? 0 : sh[t - 1];
    for (int i = begin; i < end; i++) {
        int c = g_cnt[i];
        g_rowptr[i] = run;
        g_pos[i] = run;
        run += c;
    }
    if (t == T - 1) g_rowptr[NN] = run;
}
__global__ void scatter_kernel(const int* __restrict__ ei) {
    int i = blockIdx.x * blockDim.x + threadIdx.x;
    if (i >= EE) return;
    int d = ei[EE + i];
    int p = atomicAdd(&g_pos[d], 1);
    g_col[p] = ei[i];
}

// ---------------- BN stats (accumulate into slot) ----------------------------
template <int DOUT>
__global__ void stats_kernel(const float* __restrict__ xin, int stride, int slot) {
    const float* in = xin ? xin : g_out;
    constexpr int RPB = 128 / DOUT;
    int f = threadIdx.x % DOUT;
    int sub = threadIdx.x / DOUT;
    int r = blockIdx.x * RPB + sub;
    int step = gridDim.x * RPB;
    float s = 0.f, q = 0.f;
    for (; r < NN; r += step) {
        float v = in[(size_t)r * stride + f];
        s += v;
        q = fmaf(v, v, q);
    }
    atomicAdd(&g_stats[slot * 256 + f], (double)s);
    atomicAdd(&g_stats[slot * 256 + 128 + f], (double)q);
}

// ---------------- logits via va vectors (layer 1) ----------------------------
template <int DIN, int C, bool RELU>
__global__ void valogits_kernel(const float* __restrict__ xin, int istride, int slot,
                                const float* __restrict__ W,
                                const float* __restrict__ as,
                                const float* __restrict__ ad,
                                const float* __restrict__ g,
                                const float* __restrict__ be) {
    constexpr int DOUT = 4 * C;
    const float* in = xin ? xin : g_out;
    __shared__ float vas[4][DIN], vad[4][DIN];
    __shared__ float sc[DIN], sb[DIN];
    int tid = threadIdx.x;
    for (int e = tid; e < 8 * DIN; e += 256) {
        int which = e / (4 * DIN);
        int rem = e % (4 * DIN);
        int h = rem / DIN, k = rem % DIN;
        const float* av = which ? ad : as;
        float sum = 0.f;
        for (int c = 0; c < C; c++)
            sum = fmaf(W[k * DOUT + h * C + c], av[h * C + c], sum);
        if (which) vad[h][k] = sum; else vas[h][k] = sum;
    }
    if (tid < DIN) bn_from_stats(tid, slot, g, be, sc, sb);
    __syncthreads();
    int n = blockIdx.x * 256 + tid;
    if (n >= NN) return;
    float accs[4] = {0.f, 0.f, 0.f, 0.f};
    float accd[4] = {0.f, 0.f, 0.f, 0.f};
    const float* row = in + (size_t)n * istride;
#pragma unroll 4
    for (int k = 0; k < DIN; k++) {
        float a = fmaf(row[k], sc[k], sb[k]);
        if (RELU) a = fmaxf(a, 0.f);
#pragma unroll
        for (int h = 0; h < 4; h++) {
            accs[h] = fmaf(a, vas[h][k], accs[h]);
            accd[h] = fmaf(a, vad[h][k], accd[h]);
        }
    }
    *(float4*)(g_als + n * 4) = make_float4(accs[0], accs[1], accs[2], accs[3]);
    *(float4*)(g_ald + n * 4) = make_float4(accd[0], accd[1], accd[2], accd[3]);
}

// ---------------- layer-1 input-space aggregation + fused projection ---------
// Aggregates bn(x[src,0:4]) with per-head weights (EPW=32, 16B gathers), then
// projects 16 -> 64 in-warp (every lane holds the full agg row post-butterfly).
__global__ void __launch_bounds__(256) agg_in4_kernel(const float* __restrict__ x,
                                                      const float* __restrict__ W,
                                                      const float* __restrict__ g0,
                                                      const float* __restrict__ be0) {
    __shared__ float4 s_w[8][SCAP];
    __shared__ int    s_src[8][SCAP];
    __shared__ float  Ws[4 * 64];
    __shared__ float  scs[4], sbs[4];
    int tid = threadIdx.x;
    for (int i = tid; i < 4 * 64; i += 256) Ws[i] = W[i];
    if (tid < 4) bn_from_stats(tid, 0, g0, be0, scs, sbs);
    __syncthreads();

    int wib = tid >> 5;
    int warp = (blockIdx.x * blockDim.x + tid) >> 5;
    int lane = tid & 31;
    if (warp >= NN) return;
    int n = warp;
    int start = g_rowptr[n];
    int deg = g_rowptr[n + 1] - start;
    float4 ald4 = *(const float4*)(g_ald + n * 4);

    float4 s4;
    bool fits = weight_stage(n, start, deg, ald4, lane,
                             &s_w[wib][0], &s_src[wib][0], s4);

    float4 sc4 = make_float4(scs[0], scs[1], scs[2], scs[3]);
    float4 sb4 = make_float4(sbs[0], sbs[1], sbs[2], sbs[3]);

    float4 acc0 = make_float4(0.f,0.f,0.f,0.f), acc1 = acc0, acc2 = acc0, acc3 = acc0;
    if (fits) {
#pragma unroll 2
        for (int i = lane; i <= deg; i += 32) {
            int s = s_src[wib][i];
            float4 w4 = s_w[wib][i];
            const float* p = x + (size_t)s * 22;
            float2 u0 = *(const float2*)p;
            float2 u1 = *(const float2*)(p + 2);
            float4 v = make_float4(fmaf(u0.x, sc4.x, sb4.x), fmaf(u0.y, sc4.y, sb4.y),
                                   fmaf(u1.x, sc4.z, sb4.z), fmaf(u1.y, sc4.w, sb4.w));
            acc0.x = fmaf(v.x, w4.x, acc0.x); acc0.y = fmaf(v.y, w4.x, acc0.y);
            acc0.z = fmaf(v.z, w4.x, acc0.z); acc0.w = fmaf(v.w, w4.x, acc0.w);
            acc1.x = fmaf(v.x, w4.y, acc1.x); acc1.y = fmaf(v.y, w4.y, acc1.y);
            acc1.z = fmaf(v.z, w4.y, acc1.z); acc1.w = fmaf(v.w, w4.y, acc1.w);
            acc2.x = fmaf(v.x, w4.z, acc2.x); acc2.y = fmaf(v.y, w4.z, acc2.y);
            acc2.z = fmaf(v.z, w4.z, acc2.z); acc2.w = fmaf(v.w, w4.z, acc2.w);
            acc3.x = fmaf(v.x, w4.w, acc3.x); acc3.y = fmaf(v.y, w4.w, acc3.y);
            acc3.z = fmaf(v.z, w4.w, acc3.z); acc3.w = fmaf(v.w, w4.w, acc3.w);
        }
    } else {
        for (int i = lane; i <= deg; i += 32) {
            int s = (i < deg) ? g_col[start + i] : n;
            float4 a = *(const float4*)(g_als + (size_t)s * 4);
            float4 e = lrelu4add(a, ald4);
            float4 w4 = make_float4(__expf(e.x), __expf(e.y), __expf(e.z), __expf(e.w));
            const float* p = x + (size_t)s * 22;
            float2 u0 = *(const float2*)p;
            float2 u1 = *(const float2*)(p + 2);
            float4 v = make_float4(fmaf(u0.x, sc4.x, sb4.x), fmaf(u0.y, sc4.y, sb4.y),
                                   fmaf(u1.x, sc4.z, sb4.z), fmaf(u1.y, sc4.w, sb4.w));
            acc0.x = fmaf(v.x, w4.x, acc0.x); acc0.y = fmaf(v.y, w4.x, acc0.y);
            acc0.z = fmaf(v.z, w4.x, acc0.z); acc0.w = fmaf(v.w, w4.x, acc0.w);
            acc1.x = fmaf(v.x, w4.y, acc1.x); acc1.y = fmaf(v.y, w4.y, acc1.y);
            acc1.z = fmaf(v.z, w4.y, acc1.z); acc1.w = fmaf(v.w, w4.y, acc1.w);
            acc2.x = fmaf(v.x, w4.z, acc2.x); acc2.y = fmaf(v.y, w4.z, acc2.y);
            acc2.z = fmaf(v.z, w4.z, acc2.z); acc2.w = fmaf(v.w, w4.z, acc2.w);
            acc3.x = fmaf(v.x, w4.w, acc3.x); acc3.y = fmaf(v.y, w4.w, acc3.y);
            acc3.z = fmaf(v.z, w4.w, acc3.z); acc3.w = fmaf(v.w, w4.w, acc3.w);
        }
    }
    warpSum4(acc0); warpSum4(acc1); warpSum4(acc2); warpSum4(acc3);
    // all lanes now hold the full agg row; normalize in-lane
    float4 inv = make_float4(1.f / (s4.x + 1e-16f), 1.f / (s4.y + 1e-16f),
                             1.f / (s4.z + 1e-16f), 1.f / (s4.w + 1e-16f));
    acc0.x *= inv.x; acc0.y *= inv.x; acc0.z *= inv.x; acc0.w *= inv.x;
    acc1.x *= inv.y; acc1.y *= inv.y; acc1.z *= inv.y; acc1.w *= inv.y;
    acc2.x *= inv.z; acc2.y *= inv.z; acc2.z *= inv.z; acc2.w *= inv.z;
    acc3.x *= inv.w; acc3.y *= inv.w; acc3.z *= inv.w; acc3.w *= inv.w;

    // fused projection: lane computes cols c0=2*lane, c1=c0+1 (head = lane/8)
    int h = lane >> 3;
    float4 ah = (h == 0) ? acc0 : (h == 1) ? acc1 : (h == 2) ? acc2 : acc3;
    int c0 = lane * 2;
    float o0 = ah.x * Ws[0 * 64 + c0] + ah.y * Ws[1 * 64 + c0]
             + ah.z * Ws[2 * 64 + c0] + ah.w * Ws[3 * 64 + c0];
    float o1 = ah.x * Ws[0 * 64 + c0 + 1] + ah.y * Ws[1 * 64 + c0 + 1]
             + ah.z * Ws[2 * 64 + c0 + 1] + ah.w * Ws[3 * 64 + c0 + 1];
    *(float2*)(g_out + (size_t)n * 64 + c0) = make_float2(o0, o1);
}

// ---------------- GEMM + attention-logit epilogue (2 rows/thread, LDS.128) ---
template <int DIN, int DOUT, bool RELU>
__global__ void __launch_bounds__(256) gemm_kernel(
                            const float* __restrict__ Wg,
                            const float* __restrict__ asg,
                            const float* __restrict__ adg,
                            const float* __restrict__ g,
                            const float* __restrict__ be,
                            int slot) {
    const float* in = g_out;
    constexpr int R = DOUT / 32;          // threads per row-pair (each 32 cols)
    constexpr int ROWS = 2 * (256 / R);   // rows per block
    constexpr int C = DOUT / 4;
    constexpr int HPT = 32 / C;
    __shared__ __align__(16) float Ws[DIN * DOUT];
    __shared__ float as_sh[DOUT], ad_sh[DOUT];
    __shared__ float sc_sh[DIN], sb_sh[DIN];
    int tid = threadIdx.x;
    for (int i = tid; i < DIN * DOUT; i += 256) Ws[i] = Wg[i];
    if (tid < DOUT) { as_sh[tid] = asg[tid]; ad_sh[tid] = adg[tid]; }
    if (tid < DIN)  bn_from_stats(tid, slot, g, be, sc_sh, sb_sh);
    __syncthreads();
    int r0 = blockIdx.x * ROWS + 2 * (tid / R);
    int cg = tid % R;
    if (r0 >= NN) return;
    bool has1 = (r0 + 1 < NN);
    int r1 = has1 ? (r0 + 1) : r0;

    float acc0[32], acc1[32];
#pragma unroll
    for (int j = 0; j < 32; j++) { acc0[j] = 0.f; acc1[j] = 0.f; }
    const float* i0 = in + (size_t)r0 * DIN;
    const float* i1 = in + (size_t)r1 * DIN;
    const float* wp = Ws + cg * 32;
#pragma unroll 2
    for (int k = 0; k < DIN; k++) {
        float a0 = fmaf(i0[k], sc_sh[k], sb_sh[k]);
        float a1 = fmaf(i1[k], sc_sh[k], sb_sh[k]);
        if (RELU) { a0 = fmaxf(a0, 0.f); a1 = fmaxf(a1, 0.f); }
        const float4* wv = (const float4*)(wp + k * DOUT);
#pragma unroll
        for (int j4 = 0; j4 < 8; j4++) {
            float4 w = wv[j4];
            acc0[4*j4+0] = fmaf(a0, w.x, acc0[4*j4+0]);
            acc0[4*j4+1] = fmaf(a0, w.y, acc0[4*j4+1]);
            acc0[4*j4+2] = fmaf(a0, w.z, acc0[4*j4+2]);
            acc0[4*j4+3] = fmaf(a0, w.w, acc0[4*j4+3]);
            acc1[4*j4+0] = fmaf(a1, w.x, acc1[4*j4+0]);
            acc1[4*j4+1] = fmaf(a1, w.y, acc1[4*j4+1]);
            acc1[4*j4+2] = fmaf(a1, w.z, acc1[4*j4+2]);
            acc1[4*j4+3] = fmaf(a1, w.w, acc1[4*j4+3]);
        }
    }
    // store h rows
    float4* hp0 = (float4*)(g_h + (size_t)r0 * DOUT + cg * 32);
#pragma unroll
    for (int q = 0; q < 8; q++)
        hp0[q] = make_float4(acc0[4*q], acc0[4*q+1], acc0[4*q+2], acc0[4*q+3]);
    if (has1) {
        float4* hp1 = (float4*)(g_h + (size_t)r1 * DOUT + cg * 32);
#pragma unroll
        for (int q = 0; q < 8; q++)
            hp1[q] = make_float4(acc1[4*q], acc1[4*q+1], acc1[4*q+2], acc1[4*q+3]);
    }
    // logits
#pragma unroll
    for (int u = 0; u < HPT; u++) {
        float ss0 = 0.f, dd0 = 0.f, ss1 = 0.f, dd1 = 0.f;
#pragma unroll
        for (int j = 0; j < C; j++) {
            float aw = as_sh[cg * 32 + u * C + j];
            float dw = ad_sh[cg * 32 + u * C + j];
            ss0 = fmaf(acc0[u * C + j], aw, ss0);
            dd0 = fmaf(acc0[u * C + j], dw, dd0);
            ss1 = fmaf(acc1[u * C + j], aw, ss1);
            dd1 = fmaf(acc1[u * C + j], dw, dd1);
        }
        int head = (cg * 32) / C + u;
        g_als[r0 * 4 + head] = ss0;
        g_ald[r0 * 4 + head] = dd0;
        if (has1) {
            g_als[r1 * 4 + head] = ss1;
            g_ald[r1 * 4 + head] = dd1;
        }
    }
}

// ---------------- fused softmax + aggregation (templated VPT) ----------------
template <int DOUT, int VPT>
__global__ void __launch_bounds__(256) agg_node_kernel() {
    constexpr int C   = DOUT / 4;    // channels per head
    constexpr int LPE = DOUT / VPT;  // lanes per edge
    constexpr int EPW = 32 / LPE;    // edges in flight per warp
    constexpr int NV  = VPT / 4;     // float4 loads per lane per edge
    static_assert(VPT <= C, "lane channels must stay within one head");
    __shared__ float4 s_w[8][SCAP];
    __shared__ int    s_src[8][SCAP];
    int wib = threadIdx.x >> 5;
    int warp = (blockIdx.x * blockDim.x + threadIdx.x) >> 5;
    int lane = threadIdx.x & 31;
    if (warp >= NN) return;
    int n = warp;
    int start = g_rowptr[n];
    int deg = g_rowptr[n + 1] - start;
    float4 ald4 = *(const float4*)(g_ald + n * 4);

    float4 s4;
    bool fits = weight_stage(n, start, deg, ald4, lane,
                             &s_w[wib][0], &s_src[wib][0], s4);

    int cl = lane % LPE;            // channel block (VPT channels)
    int sg = lane / LPE;            // edge slot
    int head = (cl * VPT) / C;
    float sh   = (head == 0) ? s4.x : (head == 1) ? s4.y : (head == 2) ? s4.z : s4.w;
    float invh = 1.f / (sh + 1e-16f);

    float4 acc[NV];
#pragma unroll
    for (int v = 0; v < NV; v++) acc[v] = make_float4(0.f, 0.f, 0.f, 0.f);

    if (fits) {
        const float* swf = (const float*)&s_w[wib][0];
#pragma unroll 4
        for (int i = sg; i <= deg; i += EPW) {
            int s = s_src[wib][i];
            float w = swf[i * 4 + head];            // unnormalized weight
            const float4* hp = (const float4*)(g_h + (size_t)s * DOUT + cl * VPT);
#pragma unroll
            for (int v = 0; v < NV; v++) {
                float4 hv = hp[v];
                acc[v].x = fmaf(hv.x, w, acc[v].x);
                acc[v].y = fmaf(hv.y, w, acc[v].y);
                acc[v].z = fmaf(hv.z, w, acc[v].z);
                acc[v].w = fmaf(hv.w, w, acc[v].w);
            }
        }
    } else {
        float aldh = (head == 0) ? ald4.x : (head == 1) ? ald4.y : (head == 2) ? ald4.z : ald4.w;
        for (int i = sg; i <= deg; i += EPW) {
            int s = (i < deg) ? g_col[start + i] : n;
            float av = __ldg(&g_als[s * 4 + head]);
            float w = __expf(lrelu(av + aldh));
            const float4* hp = (const float4*)(g_h + (size_t)s * DOUT + cl * VPT);
#pragma unroll
            for (int v = 0; v < NV; v++) {
                float4 hv = hp[v];
                acc[v].x = fmaf(hv.x, w, acc[v].x);
                acc[v].y = fmaf(hv.y, w, acc[v].y);
                acc[v].z = fmaf(hv.z, w, acc[v].z);
                acc[v].w = fmaf(hv.w, w, acc[v].w);
            }
        }
    }
#pragma unroll
    for (int off = LPE; off < 32; off <<= 1) {
#pragma unroll
        for (int v = 0; v < NV; v++) {
            acc[v].x += __shfl_xor_sync(0xffffffffu, acc[v].x, off);
            acc[v].y += __shfl_xor_sync(0xffffffffu, acc[v].y, off);
            acc[v].z += __shfl_xor_sync(0xffffffffu, acc[v].z, off);
            acc[v].w += __shfl_xor_sync(0xffffffffu, acc[v].w, off);
        }
    }
    if (sg == 0) {
        float4* op = (float4*)(g_out + (size_t)n * DOUT + cl * VPT);
#pragma unroll
        for (int v = 0; v < NV; v++) {
            acc[v].x *= invh; acc[v].y *= invh; acc[v].z *= invh; acc[v].w *= invh;
            op[v] = acc[v];
        }
    }
}

// ---------------- final: bn+relu+linear(32->1) -------------------------------
__global__ void final_kernel(const float* __restrict__ ow, const float* __restrict__ ob,
                             const float* __restrict__ g, const float* __restrict__ be,
                             float* __restrict__ out) {
    __shared__ float sc[32], sb[32];
    if (threadIdx.x < 32) bn_from_stats(threadIdx.x, 4, g, be, sc, sb);
    __syncthreads();
    int n = blockIdx.x * blockDim.x + threadIdx.x;
    if (n >= NN) return;
    float acc = ob[0];
    const float4* row = (const float4*)(g_out + (size_t)n * 32);
#pragma unroll
    for (int q = 0; q < 8; q++) {
        float4 v = row[q];
        int k = 4 * q;
        float v0 = fmaxf(fmaf(v.x, sc[k + 0], sb[k + 0]), 0.f);
        float v1 = fmaxf(fmaf(v.y, sc[k + 1], sb[k + 1]), 0.f);
        float v2 = fmaxf(fmaf(v.z, sc[k + 2], sb[k + 2]), 0.f);
        float v3 = fmaxf(fmaf(v.w, sc[k + 3], sb[k + 3]), 0.f);
        acc = fmaf(v0, ow[k + 0], acc);
        acc = fmaf(v1, ow[k + 1], acc);
        acc = fmaf(v2, ow[k + 2], acc);
        acc = fmaf(v3, ow[k + 3], acc);
    }
    out[n] = acc;
}

// ---------------- launch ------------------------------------------------------
extern "C" void kernel_launch(void* const* d_in, const int* in_sizes, int n_in,
                              void* d_out, int out_size) {
    bool layB = (in_sizes[1] == 2 * EE);
    const float* x = (const float*)d_in[0];
    const int* ei = (const int*)d_in[layB ? 1 : (n_in - 1)];
    int base = layB ? 2 : 1;
    const float *W[4], *As[4], *Ad[4], *G[4], *Be[4];
    for (int l = 0; l < 4; l++) {
        int b = base + 6 * l;
        W[l]  = (const float*)d_in[b];
        As[l] = (const float*)d_in[b + 1];
        Ad[l] = (const float*)d_in[b + 2];
        G[l]  = (const float*)d_in[b + 4];
        Be[l] = (const float*)d_in[b + 5];
    }
    int tb = base + 24;
    const float* g0  = (const float*)d_in[tb];
    const float* be0 = (const float*)d_in[tb + 1];
    const float* ow  = (const float*)d_in[tb + 2];
    const float* ob  = (const float*)d_in[tb + 3];
    float* out = (float*)d_out;

    const int TPB = 256;
    int egrid = (EE + TPB - 1) / TPB;
    int wgrid = (NN * 32 + TPB - 1) / TPB;   // warp per node

    // CSR build + stats-slot zero (edges shared by all layers)
    zero_cnt_kernel<<<(NN + TPB - 1) / TPB, TPB>>>();
    hist_kernel<<<egrid, TPB>>>(ei);
    scan_kernel<<<1, 1024>>>();
    scatter_kernel<<<egrid, TPB>>>(ei);

    // input BN stats (x[:, :4], stride 22) -> slot 0
    stats_kernel<4><<<1024, 128>>>(x, 22, 0);

    // layer 1: 4 -> 64 (input-space aggregation + fused projection)
    valogits_kernel<4, 16, false><<<(NN + 255) / 256, 256>>>(x, 22, 0, W[0], As[0], Ad[0], g0, be0);
    agg_in4_kernel<<<wgrid, TPB>>>(x, W[0], g0, be0);
    stats_kernel<64><<<1024, 128>>>(nullptr, 64, 1);

    // layer 2: 64 -> 128
    gemm_kernel<64, 128, true><<<(NN + 127) / 128, 256>>>(W[1], As[1], Ad[1], G[0], Be[0], 1);
    agg_node_kernel<128, 16><<<wgrid, TPB>>>();
    stats_kernel<128><<<1024, 128>>>(nullptr, 128, 2);

    // layer 3: 128 -> 64
    gemm_kernel<128, 64, true><<<(NN + 255) / 256, 256>>>(W[2], As[2], Ad[2], G[1], Be[1], 2);
    agg_node_kernel<64, 8><<<wgrid, TPB>>>();
    stats_kernel<64><<<1024, 128>>>(nullptr, 64, 3);

    // layer 4: 64 -> 32
    gemm_kernel<64, 32, true><<<(NN + 511) / 512, 256>>>(W[3], As[3], Ad[3], G[2], Be[2], 3);
    agg_node_kernel<32, 8><<<wgrid, TPB>>>();
    stats_kernel<32><<<1024, 128>>>(nullptr, 32, 4);

    // output head (BN from slot 4)
    final_kernel<<<(NN + 255) / 256, 256>>>(ow, ob, G[3], Be[3], out);
}

// round 14
// speedup vs baseline: 1.9554x; 1.0977x over previous
#include <cuda_runtime.h>
#include <cuda_fp16.h>
#include <cstdint>
#include <cstddef>
#include <math.h>

#define NN 100000
#define EE 1600000
#define SCAP 48          // staged edges per node (deg+1 <= SCAP); fallback beyond

// ---------------- scratch (device globals) -----------------------------------
__device__ __align__(16) __half g_h16[(size_t)NN * 128];  // GEMM output (fp16 storage)
__device__ __align__(16) float g_out[(size_t)NN * 128];   // aggregation output
__device__ __align__(16) float g_als[NN * 4];
__device__ __align__(16) float g_ald[NN * 4];
__device__ double g_stats[5 * 256];                       // 5 BN slots: [f]=sum,[128+f]=sumsq
__device__ int g_cnt[NN];
__device__ int g_rowptr[NN + 1];
__device__ int g_pos[NN];
__device__ int g_col[EE];

// ---------------- helpers ----------------------------------------------------
__device__ __forceinline__ float lrelu(float x) { return x > 0.f ? x : 0.2f * x; }

__device__ __forceinline__ float4 lrelu4add(float4 a, float4 b) {
    return make_float4(lrelu(a.x + b.x), lrelu(a.y + b.y), lrelu(a.z + b.z), lrelu(a.w + b.w));
}
__device__ __forceinline__ void warpSum4(float4& s) {
#pragma unroll
    for (int off = 16; off >= 1; off >>= 1) {
        s.x += __shfl_xor_sync(0xffffffffu, s.x, off);
        s.y += __shfl_xor_sync(0xffffffffu, s.y, off);
        s.z += __shfl_xor_sync(0xffffffffu, s.z, off);
        s.w += __shfl_xor_sync(0xffffffffu, s.w, off);
    }
}
__device__ __forceinline__ uint32_t f2h2(float a, float b) {
    __half2 h = __floats2half2_rn(a, b);
    return *(uint32_t*)&h;
}
__device__ __forceinline__ float2 h2f2(uint32_t u) {
    return __half22float2(*(__half2*)&u);
}

// Per-block BN scale/bias from stats slot (deterministic; identical in all blocks).
__device__ __forceinline__ void bn_from_stats(int f, int slot,
                                              const float* g, const float* be,
                                              float* sc_sh, float* sb_sh) {
    const double* st = g_stats + slot * 256;
    double mu = st[f] / (double)NN;
    double var = st[128 + f] / (double)NN - mu * mu;
    if (var < 0.0) var = 0.0;
    float sc = g[f] * rsqrtf((float)var + 1e-5f);
    sc_sh[f] = sc;
    sb_sh[f] = be[f] - (float)mu * sc;
}

// Single-pass exp-weight staging (no max subtraction; logits bounded).
// Stages (src, exp_weight4) into smem; outputs s4 = per-head exp-sum (all lanes).
__device__ __forceinline__ bool weight_stage(
    int n, int start, int deg, float4 ald4, int lane,
    float4* sal, int* ssrc, float4& s4)
{
    bool fits = (deg < SCAP);
    s4 = make_float4(0.f, 0.f, 0.f, 0.f);
    for (int i = lane; i <= deg; i += 32) {
        int s = (i < deg) ? __ldg(&g_col[start + i]) : n;
        float4 a = *(const float4*)(g_als + (size_t)s * 4);
        float4 e = lrelu4add(a, ald4);
        float4 x = make_float4(__expf(e.x), __expf(e.y), __expf(e.z), __expf(e.w));
        s4.x += x.x; s4.y += x.y; s4.z += x.z; s4.w += x.w;
        if (fits) { sal[i] = x; ssrc[i] = s; }
    }
    warpSum4(s4);
    __syncwarp();
    return fits;
}

// ---------------- CSR build + stats zero -------------------------------------
__global__ void zero_cnt_kernel() {
    int i = blockIdx.x * blockDim.x + threadIdx.x;
    if (i < NN) g_cnt[i] = 0;
    if (i < 5 * 256) g_stats[i] = 0.0;
}
__global__ void hist_kernel(const int* __restrict__ ei) {
    int i = blockIdx.x * blockDim.x + threadIdx.x;
    if (i < EE) atomicAdd(&g_cnt[ei[EE + i]], 1);
}
__global__ void scan_kernel() {
    __shared__ int sh[1024];
    const int T = 1024;
    const int per = (NN + T - 1) / T;
    int t = threadIdx.x;
    int begin = t * per;
    int end = begin + per; if (end > NN) end = NN;
    int sum = 0;
    for (int i = begin; i < end; i++) sum += g_cnt[i];
    sh[t] = sum;
    __syncthreads();
    for (int off = 1; off < T; off <<= 1) {
        int v = (t >= off) ? sh[t - off] : 0;
        __syncthreads();
        sh[t] += v;
        __syncthreads();
    }
    int run = (t == 0) ? 0 : sh[t - 1];
    for (int i = begin; i < end; i++) {
        int c = g_cnt[i];
        g_rowptr[i] = run;
        g_pos[i] = run;
        run += c;
    }
    if (t == T - 1) g_rowptr[NN] = run;
}
__global__ void scatter_kernel(const int* __restrict__ ei) {
    int i = blockIdx.x * blockDim.x + threadIdx.x;
    if (i >= EE) return;
    int d = ei[EE + i];
    int p = atomicAdd(&g_pos[d], 1);
    g_col[p] = ei[i];
}

// ---------------- BN stats (accumulate into slot) ----------------------------
template <int DOUT>
__global__ void stats_kernel(const float* __restrict__ xin, int stride, int slot) {
    const float* in = xin ? xin : g_out;
    constexpr int RPB = 128 / DOUT;
    int f = threadIdx.x % DOUT;
    int sub = threadIdx.x / DOUT;
    int r = blockIdx.x * RPB + sub;
    int step = gridDim.x * RPB;
    float s = 0.f, q = 0.f;
    for (; r < NN; r += step) {
        float v = in[(size_t)r * stride + f];
        s += v;
        q = fmaf(v, v, q);
    }
    atomicAdd(&g_stats[slot * 256 + f], (double)s);
    atomicAdd(&g_stats[slot * 256 + 128 + f], (double)q);
}

// ---------------- logits via va vectors (layer 1) ----------------------------
template <int DIN, int C, bool RELU>
__global__ void valogits_kernel(const float* __restrict__ xin, int istride, int slot,
                                const float* __restrict__ W,
                                const float* __restrict__ as,
                                const float* __restrict__ ad,
                                const float* __restrict__ g,
                                const float* __restrict__ be) {
    constexpr int DOUT = 4 * C;
    const float* in = xin ? xin : g_out;
    __shared__ float vas[4][DIN], vad[4][DIN];
    __shared__ float sc[DIN], sb[DIN];
    int tid = threadIdx.x;
    for (int e = tid; e < 8 * DIN; e += 256) {
        int which = e / (4 * DIN);
        int rem = e % (4 * DIN);
        int h = rem / DIN, k = rem % DIN;
        const float* av = which ? ad : as;
        float sum = 0.f;
        for (int c = 0; c < C; c++)
            sum = fmaf(W[k * DOUT + h * C + c], av[h * C + c], sum);
        if (which) vad[h][k] = sum; else vas[h][k] = sum;
    }
    if (tid < DIN) bn_from_stats(tid, slot, g, be, sc, sb);
    __syncthreads();
    int n = blockIdx.x * 256 + tid;
    if (n >= NN) return;
    float accs[4] = {0.f, 0.f, 0.f, 0.f};
    float accd[4] = {0.f, 0.f, 0.f, 0.f};
    const float* row = in + (size_t)n * istride;
#pragma unroll 4
    for (int k = 0; k < DIN; k++) {
        float a = fmaf(row[k], sc[k], sb[k]);
        if (RELU) a = fmaxf(a, 0.f);
#pragma unroll
        for (int h = 0; h < 4; h++) {
            accs[h] = fmaf(a, vas[h][k], accs[h]);
            accd[h] = fmaf(a, vad[h][k], accd[h]);
        }
    }
    *(float4*)(g_als + n * 4) = make_float4(accs[0], accs[1], accs[2], accs[3]);
    *(float4*)(g_ald + n * 4) = make_float4(accd[0], accd[1], accd[2], accd[3]);
}

// ---------------- layer-1 input-space aggregation + fused projection ---------
__global__ void __launch_bounds__(256) agg_in4_kernel(const float* __restrict__ x,
                                                      const float* __restrict__ W,
                                                      const float* __restrict__ g0,
                                                      const float* __restrict__ be0) {
    __shared__ float4 s_w[8][SCAP];
    __shared__ int    s_src[8][SCAP];
    __shared__ float  Ws[4 * 64];
    __shared__ float  scs[4], sbs[4];
    int tid = threadIdx.x;
    for (int i = tid; i < 4 * 64; i += 256) Ws[i] = W[i];
    if (tid < 4) bn_from_stats(tid, 0, g0, be0, scs, sbs);
    __syncthreads();

    int wib = tid >> 5;
    int warp = (blockIdx.x * blockDim.x + tid) >> 5;
    int lane = tid & 31;
    if (warp >= NN) return;
    int n = warp;
    int start = g_rowptr[n];
    int deg = g_rowptr[n + 1] - start;
    float4 ald4 = *(const float4*)(g_ald + n * 4);

    float4 s4;
    bool fits = weight_stage(n, start, deg, ald4, lane,
                             &s_w[wib][0], &s_src[wib][0], s4);

    float4 sc4 = make_float4(scs[0], scs[1], scs[2], scs[3]);
    float4 sb4 = make_float4(sbs[0], sbs[1], sbs[2], sbs[3]);

    float4 acc0 = make_float4(0.f,0.f,0.f,0.f), acc1 = acc0, acc2 = acc0, acc3 = acc0;
    if (fits) {
#pragma unroll 2
        for (int i = lane; i <= deg; i += 32) {
            int s = s_src[wib][i];
            float4 w4 = s_w[wib][i];
            const float* p = x + (size_t)s * 22;
            float2 u0 = *(const float2*)p;
            float2 u1 = *(const float2*)(p + 2);
            float4 v = make_float4(fmaf(u0.x, sc4.x, sb4.x), fmaf(u0.y, sc4.y, sb4.y),
                                   fmaf(u1.x, sc4.z, sb4.z), fmaf(u1.y, sc4.w, sb4.w));
            acc0.x = fmaf(v.x, w4.x, acc0.x); acc0.y = fmaf(v.y, w4.x, acc0.y);
            acc0.z = fmaf(v.z, w4.x, acc0.z); acc0.w = fmaf(v.w, w4.x, acc0.w);
            acc1.x = fmaf(v.x, w4.y, acc1.x); acc1.y = fmaf(v.y, w4.y, acc1.y);
            acc1.z = fmaf(v.z, w4.y, acc1.z); acc1.w = fmaf(v.w, w4.y, acc1.w);
            acc2.x = fmaf(v.x, w4.z, acc2.x); acc2.y = fmaf(v.y, w4.z, acc2.y);
            acc2.z = fmaf(v.z, w4.z, acc2.z); acc2.w = fmaf(v.w, w4.z, acc2.w);
            acc3.x = fmaf(v.x, w4.w, acc3.x); acc3.y = fmaf(v.y, w4.w, acc3.y);
            acc3.z = fmaf(v.z, w4.w, acc3.z); acc3.w = fmaf(v.w, w4.w, acc3.w);
        }
    } else {
        for (int i = lane; i <= deg; i += 32) {
            int s = (i < deg) ? g_col[start + i] : n;
            float4 a = *(const float4*)(g_als + (size_t)s * 4);
            float4 e = lrelu4add(a, ald4);
            float4 w4 = make_float4(__expf(e.x), __expf(e.y), __expf(e.z), __expf(e.w));
            const float* p = x + (size_t)s * 22;
            float2 u0 = *(const float2*)p;
            float2 u1 = *(const float2*)(p + 2);
            float4 v = make_float4(fmaf(u0.x, sc4.x, sb4.x), fmaf(u0.y, sc4.y, sb4.y),
                                   fmaf(u1.x, sc4.z, sb4.z), fmaf(u1.y, sc4.w, sb4.w));
            acc0.x = fmaf(v.x, w4.x, acc0.x); acc0.y = fmaf(v.y, w4.x, acc0.y);
            acc0.z = fmaf(v.z, w4.x, acc0.z); acc0.w = fmaf(v.w, w4.x, acc0.w);
            acc1.x = fmaf(v.x, w4.y, acc1.x); acc1.y = fmaf(v.y, w4.y, acc1.y);
            acc1.z = fmaf(v.z, w4.y, acc1.z); acc1.w = fmaf(v.w, w4.y, acc1.w);
            acc2.x = fmaf(v.x, w4.z, acc2.x); acc2.y = fmaf(v.y, w4.z, acc2.y);
            acc2.z = fmaf(v.z, w4.z, acc2.z); acc2.w = fmaf(v.w, w4.z, acc2.w);
            acc3.x = fmaf(v.x, w4.w, acc3.x); acc3.y = fmaf(v.y, w4.w, acc3.y);
            acc3.z = fmaf(v.z, w4.w, acc3.z); acc3.w = fmaf(v.w, w4.w, acc3.w);
        }
    }
    warpSum4(acc0); warpSum4(acc1); warpSum4(acc2); warpSum4(acc3);
    float4 inv = make_float4(1.f / (s4.x + 1e-16f), 1.f / (s4.y + 1e-16f),
                             1.f / (s4.z + 1e-16f), 1.f / (s4.w + 1e-16f));
    acc0.x *= inv.x; acc0.y *= inv.x; acc0.z *= inv.x; acc0.w *= inv.x;
    acc1.x *= inv.y; acc1.y *= inv.y; acc1.z *= inv.y; acc1.w *= inv.y;
    acc2.x *= inv.z; acc2.y *= inv.z; acc2.z *= inv.z; acc2.w *= inv.z;
    acc3.x *= inv.w; acc3.y *= inv.w; acc3.z *= inv.w; acc3.w *= inv.w;

    // fused projection: lane computes cols c0=2*lane, c1=c0+1 (head = lane/8)
    int h = lane >> 3;
    float4 ah = (h == 0) ? acc0 : (h == 1) ? acc1 : (h == 2) ? acc2 : acc3;
    int c0 = lane * 2;
    float o0 = ah.x * Ws[0 * 64 + c0] + ah.y * Ws[1 * 64 + c0]
             + ah.z * Ws[2 * 64 + c0] + ah.w * Ws[3 * 64 + c0];
    float o1 = ah.x * Ws[0 * 64 + c0 + 1] + ah.y * Ws[1 * 64 + c0 + 1]
             + ah.z * Ws[2 * 64 + c0 + 1] + ah.w * Ws[3 * 64 + c0 + 1];
    *(float2*)(g_out + (size_t)n * 64 + c0) = make_float2(o0, o1);
}

// ---------------- GEMM + attention-logit epilogue (2 rows/thread, fp16 h) ----
template <int DIN, int DOUT, bool RELU>
__global__ void __launch_bounds__(256) gemm_kernel(
                            const float* __restrict__ Wg,
                            const float* __restrict__ asg,
                            const float* __restrict__ adg,
                            const float* __restrict__ g,
                            const float* __restrict__ be,
                            int slot) {
    const float* in = g_out;
    constexpr int R = DOUT / 32;          // threads per row-pair (each 32 cols)
    constexpr int ROWS = 2 * (256 / R);   // rows per block
    constexpr int C = DOUT / 4;
    constexpr int HPT = 32 / C;
    __shared__ __align__(16) float Ws[DIN * DOUT];
    __shared__ float as_sh[DOUT], ad_sh[DOUT];
    __shared__ float sc_sh[DIN], sb_sh[DIN];
    int tid = threadIdx.x;
    for (int i = tid; i < DIN * DOUT; i += 256) Ws[i] = Wg[i];
    if (tid < DOUT) { as_sh[tid] = asg[tid]; ad_sh[tid] = adg[tid]; }
    if (tid < DIN)  bn_from_stats(tid, slot, g, be, sc_sh, sb_sh);
    __syncthreads();
    int r0 = blockIdx.x * ROWS + 2 * (tid / R);
    int cg = tid % R;
    if (r0 >= NN) return;
    bool has1 = (r0 + 1 < NN);
    int r1 = has1 ? (r0 + 1) : r0;

    float acc0[32], acc1[32];
#pragma unroll
    for (int j = 0; j < 32; j++) { acc0[j] = 0.f; acc1[j] = 0.f; }
    const float* i0 = in + (size_t)r0 * DIN;
    const float* i1 = in + (size_t)r1 * DIN;
    const float* wp = Ws + cg * 32;
#pragma unroll 2
    for (int k = 0; k < DIN; k++) {
        float a0 = fmaf(i0[k], sc_sh[k], sb_sh[k]);
        float a1 = fmaf(i1[k], sc_sh[k], sb_sh[k]);
        if (RELU) { a0 = fmaxf(a0, 0.f); a1 = fmaxf(a1, 0.f); }
        const float4* wv = (const float4*)(wp + k * DOUT);
#pragma unroll
        for (int j4 = 0; j4 < 8; j4++) {
            float4 w = wv[j4];
            acc0[4*j4+0] = fmaf(a0, w.x, acc0[4*j4+0]);
            acc0[4*j4+1] = fmaf(a0, w.y, acc0[4*j4+1]);
            acc0[4*j4+2] = fmaf(a0, w.z, acc0[4*j4+2]);
            acc0[4*j4+3] = fmaf(a0, w.w, acc0[4*j4+3]);
            acc1[4*j4+0] = fmaf(a1, w.x, acc1[4*j4+0]);
            acc1[4*j4+1] = fmaf(a1, w.y, acc1[4*j4+1]);
            acc1[4*j4+2] = fmaf(a1, w.z, acc1[4*j4+2]);
            acc1[4*j4+3] = fmaf(a1, w.w, acc1[4*j4+3]);
        }
    }
    // store h rows as fp16 (4x uint4 = 32 halfs)
    {
        uint4* hp0 = (uint4*)((__half*)g_h16 + (size_t)r0 * DOUT + cg * 32);
#pragma unroll
        for (int q = 0; q < 4; q++) {
            uint4 u;
            u.x = f2h2(acc0[8*q+0], acc0[8*q+1]);
            u.y = f2h2(acc0[8*q+2], acc0[8*q+3]);
            u.z = f2h2(acc0[8*q+4], acc0[8*q+5]);
            u.w = f2h2(acc0[8*q+6], acc0[8*q+7]);
            hp0[q] = u;
        }
        if (has1) {
            uint4* hp1 = (uint4*)((__half*)g_h16 + (size_t)r1 * DOUT + cg * 32);
#pragma unroll
            for (int q = 0; q < 4; q++) {
                uint4 u;
                u.x = f2h2(acc1[8*q+0], acc1[8*q+1]);
                u.y = f2h2(acc1[8*q+2], acc1[8*q+3]);
                u.z = f2h2(acc1[8*q+4], acc1[8*q+5]);
                u.w = f2h2(acc1[8*q+6], acc1[8*q+7]);
                hp1[q] = u;
            }
        }
    }
    // logits (fp32 accumulators — full precision)
#pragma unroll
    for (int u = 0; u < HPT; u++) {
        float ss0 = 0.f, dd0 = 0.f, ss1 = 0.f, dd1 = 0.f;
#pragma unroll
        for (int j = 0; j < C; j++) {
            float aw = as_sh[cg * 32 + u * C + j];
            float dw = ad_sh[cg * 32 + u * C + j];
            ss0 = fmaf(acc0[u * C + j], aw, ss0);
            dd0 = fmaf(acc0[u * C + j], dw, dd0);
            ss1 = fmaf(acc1[u * C + j], aw, ss1);
            dd1 = fmaf(acc1[u * C + j], dw, dd1);
        }
        int head = (cg * 32) / C + u;
        g_als[r0 * 4 + head] = ss0;
        g_ald[r0 * 4 + head] = dd0;
        if (has1) {
            g_als[r1 * 4 + head] = ss1;
            g_ald[r1 * 4 + head] = dd1;
        }
    }
}

// ---------------- fused softmax + aggregation (fp16 h gathers) ---------------
template <int DOUT, int VPT>
__global__ void __launch_bounds__(256) agg_node_kernel() {
    constexpr int C   = DOUT / 4;    // channels per head
    constexpr int LPE = DOUT / VPT;  // lanes per edge
    constexpr int EPW = 32 / LPE;    // edges in flight per warp
    constexpr int NV  = VPT / 8;     // uint4 (8-half) loads per lane per edge
    static_assert(VPT <= C, "lane channels must stay within one head");
    static_assert(VPT >= 8, "need at least one uint4 per lane");
    __shared__ float4 s_w[8][SCAP];
    __shared__ int    s_src[8][SCAP];
    int wib = threadIdx.x >> 5;
    int warp = (blockIdx.x * blockDim.x + threadIdx.x) >> 5;
    int lane = threadIdx.x & 31;
    if (warp >= NN) return;
    int n = warp;
    int start = g_rowptr[n];
    int deg = g_rowptr[n + 1] - start;
    float4 ald4 = *(const float4*)(g_ald + n * 4);

    float4 s4;
    bool fits = weight_stage(n, start, deg, ald4, lane,
                             &s_w[wib][0], &s_src[wib][0], s4);

    int cl = lane % LPE;            // channel block (VPT channels)
    int sg = lane / LPE;            // edge slot
    int head = (cl * VPT) / C;
    float sh   = (head == 0) ? s4.x : (head == 1) ? s4.y : (head == 2) ? s4.z : s4.w;
    float invh = 1.f / (sh + 1e-16f);

    float4 accA[NV], accB[NV];      // 8 floats per uint4 load
#pragma unroll
    for (int v = 0; v < NV; v++) {
        accA[v] = make_float4(0.f, 0.f, 0.f, 0.f);
        accB[v] = make_float4(0.f, 0.f, 0.f, 0.f);
    }

    if (fits) {
        const float* swf = (const float*)&s_w[wib][0];
#pragma unroll 4
        for (int i = sg; i <= deg; i += EPW) {
            int s = s_src[wib][i];
            float w = swf[i * 4 + head];            // unnormalized weight
            const uint4* hp = (const uint4*)((const __half*)g_h16 + (size_t)s * DOUT + cl * VPT);
#pragma unroll
            for (int v = 0; v < NV; v++) {
                uint4 u = hp[v];
                float2 f0 = h2f2(u.x), f1 = h2f2(u.y), f2 = h2f2(u.z), f3 = h2f2(u.w);
                accA[v].x = fmaf(f0.x, w, accA[v].x); accA[v].y = fmaf(f0.y, w, accA[v].y);
                accA[v].z = fmaf(f1.x, w, accA[v].z); accA[v].w = fmaf(f1.y, w, accA[v].w);
                accB[v].x = fmaf(f2.x, w, accB[v].x); accB[v].y = fmaf(f2.y, w, accB[v].y);
                accB[v].z = fmaf(f3.x, w, accB[v].z); accB[v].w = fmaf(f3.y, w, accB[v].w);
            }
        }
    } else {
        float aldh = (head == 0) ? ald4.x : (head == 1) ? ald4.y : (head == 2) ? ald4.z : ald4.w;
        for (int i = sg; i <= deg; i += EPW) {
            int s = (i < deg) ? g_col[start + i] : n;
            float av = __ldg(&g_als[s * 4 + head]);
            float w = __expf(lrelu(av + aldh));
            const uint4* hp = (const uint4*)((const __half*)g_h16 + (size_t)s * DOUT + cl * VPT);
#pragma unroll
            for (int v = 0; v < NV; v++) {
                uint4 u = hp[v];
                float2 f0 = h2f2(u.x), f1 = h2f2(u.y), f2 = h2f2(u.z), f3 = h2f2(u.w);
                accA[v].x = fmaf(f0.x, w, accA[v].x); accA[v].y = fmaf(f0.y, w, accA[v].y);
                accA[v].z = fmaf(f1.x, w, accA[v].z); accA[v].w = fmaf(f1.y, w, accA[v].w);
                accB[v].x = fmaf(f2.x, w, accB[v].x); accB[v].y = fmaf(f2.y, w, accB[v].y);
                accB[v].z = fmaf(f3.x, w, accB[v].z); accB[v].w = fmaf(f3.y, w, accB[v].w);
            }
        }
    }
#pragma unroll
    for (int off = LPE; off < 32; off <<= 1) {
#pragma unroll
        for (int v = 0; v < NV; v++) {
            accA[v].x += __shfl_xor_sync(0xffffffffu, accA[v].x, off);
            accA[v].y += __shfl_xor_sync(0xffffffffu, accA[v].y, off);
            accA[v].z += __shfl_xor_sync(0xffffffffu, accA[v].z, off);
            accA[v].w += __shfl_xor_sync(0xffffffffu, accA[v].w, off);
            accB[v].x += __shfl_xor_sync(0xffffffffu, accB[v].x, off);
            accB[v].y += __shfl_xor_sync(0xffffffffu, accB[v].y, off);
            accB[v].z += __shfl_xor_sync(0xffffffffu, accB[v].z, off);
            accB[v].w += __shfl_xor_sync(0xffffffffu, accB[v].w, off);
        }
    }
    if (sg == 0) {
        float4* op = (float4*)(g_out + (size_t)n * DOUT + cl * VPT);
#pragma unroll
        for (int v = 0; v < NV; v++) {
            accA[v].x *= invh; accA[v].y *= invh; accA[v].z *= invh; accA[v].w *= invh;
            accB[v].x *= invh; accB[v].y *= invh; accB[v].z *= invh; accB[v].w *= invh;
            op[2 * v + 0] = accA[v];
            op[2 * v + 1] = accB[v];
        }
    }
}

// ---------------- final: bn+relu+linear(32->1) -------------------------------
__global__ void final_kernel(const float* __restrict__ ow, const float* __restrict__ ob,
                             const float* __restrict__ g, const float* __restrict__ be,
                             float* __restrict__ out) {
    __shared__ float sc[32], sb[32];
    if (threadIdx.x < 32) bn_from_stats(threadIdx.x, 4, g, be, sc, sb);
    __syncthreads();
    int n = blockIdx.x * blockDim.x + threadIdx.x;
    if (n >= NN) return;
    float acc = ob[0];
    const float4* row = (const float4*)(g_out + (size_t)n * 32);
#pragma unroll
    for (int q = 0; q < 8; q++) {
        float4 v = row[q];
        int k = 4 * q;
        float v0 = fmaxf(fmaf(v.x, sc[k + 0], sb[k + 0]), 0.f);
        float v1 = fmaxf(fmaf(v.y, sc[k + 1], sb[k + 1]), 0.f);
        float v2 = fmaxf(fmaf(v.z, sc[k + 2], sb[k + 2]), 0.f);
        float v3 = fmaxf(fmaf(v.w, sc[k + 3], sb[k + 3]), 0.f);
        acc = fmaf(v0, ow[k + 0], acc);
        acc = fmaf(v1, ow[k + 1], acc);
        acc = fmaf(v2, ow[k + 2], acc);
        acc = fmaf(v3, ow[k + 3], acc);
    }
    out[n] = acc;
}

// ---------------- launch ------------------------------------------------------
extern "C" void kernel_launch(void* const* d_in, const int* in_sizes, int n_in,
                              void* d_out, int out_size) {
    bool layB = (in_sizes[1] == 2 * EE);
    const float* x = (const float*)d_in[0];
    const int* ei = (const int*)d_in[layB ? 1 : (n_in - 1)];
    int base = layB ? 2 : 1;
    const float *W[4], *As[4], *Ad[4], *G[4], *Be[4];
    for (int l = 0; l < 4; l++) {
        int b = base + 6 * l;
        W[l]  = (const float*)d_in[b];
        As[l] = (const float*)d_in[b + 1];
        Ad[l] = (const float*)d_in[b + 2];
        G[l]  = (const float*)d_in[b + 4];
        Be[l] = (const float*)d_in[b + 5];
    }
    int tb = base + 24;
    const float* g0  = (const float*)d_in[tb];
    const float* be0 = (const float*)d_in[tb + 1];
    const float* ow  = (const float*)d_in[tb + 2];
    const float* ob  = (const float*)d_in[tb + 3];
    float* out = (float*)d_out;

    const int TPB = 256;
    int egrid = (EE + TPB - 1) / TPB;
    int wgrid = (NN * 32 + TPB - 1) / TPB;   // warp per node

    // CSR build + stats-slot zero (edges shared by all layers)
    zero_cnt_kernel<<<(NN + TPB - 1) / TPB, TPB>>>();
    hist_kernel<<<egrid, TPB>>>(ei);
    scan_kernel<<<1, 1024>>>();
    scatter_kernel<<<egrid, TPB>>>(ei);

    // input BN stats (x[:, :4], stride 22) -> slot 0
    stats_kernel<4><<<1024, 128>>>(x, 22, 0);

    // layer 1: 4 -> 64 (input-space aggregation + fused projection)
    valogits_kernel<4, 16, false><<<(NN + 255) / 256, 256>>>(x, 22, 0, W[0], As[0], Ad[0], g0, be0);
    agg_in4_kernel<<<wgrid, TPB>>>(x, W[0], g0, be0);
    stats_kernel<64><<<1024, 128>>>(nullptr, 64, 1);

    // layer 2: 64 -> 128
    gemm_kernel<64, 128, true><<<(NN + 127) / 128, 256>>>(W[1], As[1], Ad[1], G[0], Be[0], 1);
    agg_node_kernel<128, 16><<<wgrid, TPB>>>();
    stats_kernel<128><<<1024, 128>>>(nullptr, 128, 2);

    // layer 3: 128 -> 64
    gemm_kernel<128, 64, true><<<(NN + 255) / 256, 256>>>(W[2], As[2], Ad[2], G[1], Be[1], 2);
    agg_node_kernel<64, 8><<<wgrid, TPB>>>();
    stats_kernel<64><<<1024, 128>>>(nullptr, 64, 3);

    // layer 4: 64 -> 32
    gemm_kernel<64, 32, true><<<(NN + 511) / 512, 256>>>(W[3], As[3], Ad[3], G[2], Be[2], 3);
    agg_node_kernel<32, 8><<<wgrid, TPB>>>();
    stats_kernel<32><<<1024, 128>>>(nullptr, 32, 4);

    // output head (BN from slot 4)
    final_kernel<<<(NN + 255) / 256, 256>>>(ow, ob, G[3], Be[3], out);
}

// round 16
// speedup vs baseline: 2.0817x; 1.0646x over previous
#include <cuda_runtime.h>
#include <cuda_fp16.h>
#include <cstdint>
#include <cstddef>
#include <math.h>

#define NN 100000
#define EE 1600000
#define SCAP 48          // staged edges per node (deg+1 <= SCAP); fallback beyond
#define PBLK 592         // persistent agg grid

// ---------------- scratch (device globals) -----------------------------------
__device__ __align__(16) __half g_h16[(size_t)NN * 128];  // GEMM output (fp16 storage)
__device__ __align__(16) float g_out[(size_t)NN * 128];   // aggregation output
__device__ __align__(16) float g_als[NN * 4];
__device__ __align__(16) float g_ald[NN * 4];
__device__ double g_stats[5 * 2048];                      // 5 slots x 8 shards x 256
__device__ int g_cnt[NN];
__device__ int g_rowptr[NN + 1];
__device__ int g_pos[NN];
__device__ int g_col[EE];

// ---------------- helpers ----------------------------------------------------
__device__ __forceinline__ float lrelu(float x) { return x > 0.f ? x : 0.2f * x; }

__device__ __forceinline__ float4 lrelu4add(float4 a, float4 b) {
    return make_float4(lrelu(a.x + b.x), lrelu(a.y + b.y), lrelu(a.z + b.z), lrelu(a.w + b.w));
}
__device__ __forceinline__ void warpSum4(float4& s) {
#pragma unroll
    for (int off = 16; off >= 1; off >>= 1) {
        s.x += __shfl_xor_sync(0xffffffffu, s.x, off);
        s.y += __shfl_xor_sync(0xffffffffu, s.y, off);
        s.z += __shfl_xor_sync(0xffffffffu, s.z, off);
        s.w += __shfl_xor_sync(0xffffffffu, s.w, off);
    }
}
__device__ __forceinline__ uint32_t f2h2(float a, float b) {
    __half2 h = __floats2half2_rn(a, b);
    return *(uint32_t*)&h;
}
__device__ __forceinline__ float2 h2f2(uint32_t u) {
    return __half22float2(*(__half2*)&u);
}

// Per-block BN scale/bias from sharded stats slot (deterministic everywhere).
__device__ __forceinline__ void bn_from_stats(int f, int slot,
                                              const float* g, const float* be,
                                              float* sc_sh, float* sb_sh) {
    const double* st = g_stats + slot * 2048;
    double su = 0.0, qq = 0.0;
#pragma unroll
    for (int sh = 0; sh < 8; sh++) {
        su += st[sh * 256 + f];
        qq += st[sh * 256 + 128 + f];
    }
    double mu = su / (double)NN;
    double var = qq / (double)NN - mu * mu;
    if (var < 0.0) var = 0.0;
    float sc = g[f] * rsqrtf((float)var + 1e-5f);
    sc_sh[f] = sc;
    sb_sh[f] = be[f] - (float)mu * sc;
}

// Single-pass exp-weight staging (no max subtraction; logits bounded).
__device__ __forceinline__ bool weight_stage(
    int n, int start, int deg, float4 ald4, int lane,
    float4* sal, int* ssrc, float4& s4)
{
    bool fits = (deg < SCAP);
    s4 = make_float4(0.f, 0.f, 0.f, 0.f);
    for (int i = lane; i <= deg; i += 32) {
        int s = (i < deg) ? __ldg(&g_col[start + i]) : n;
        float4 a = *(const float4*)(g_als + (size_t)s * 4);
        float4 e = lrelu4add(a, ald4);
        float4 x = make_float4(__expf(e.x), __expf(e.y), __expf(e.z), __expf(e.w));
        s4.x += x.x; s4.y += x.y; s4.z += x.z; s4.w += x.w;
        if (fits) { sal[i] = x; ssrc[i] = s; }
    }
    warpSum4(s4);
    __syncwarp();
    return fits;
}

// ---------------- CSR build + stats zero -------------------------------------
__global__ void zero_cnt_kernel() {
    int i = blockIdx.x * blockDim.x + threadIdx.x;
    if (i < NN) g_cnt[i] = 0;
    if (i < 5 * 2048) g_stats[i] = 0.0;
}
__global__ void hist_kernel(const int* __restrict__ ei) {
    int i = blockIdx.x * blockDim.x + threadIdx.x;
    if (i < EE) atomicAdd(&g_cnt[ei[EE + i]], 1);
}
__global__ void scan_kernel() {
    __shared__ int sh[1024];
    const int T = 1024;
    const int per = (NN + T - 1) / T;
    int t = threadIdx.x;
    int begin = t * per;
    int end = begin + per; if (end > NN) end = NN;
    int sum = 0;
    for (int i = begin; i < end; i++) sum += g_cnt[i];
    sh[t] = sum;
    __syncthreads();
    for (int off = 1; off < T; off <<= 1) {
        int v = (t >= off) ? sh[t - off] : 0;
        __syncthreads();
        sh[t] += v;
        __syncthreads();
    }
    int run = (t == 0) ? 0 : sh[t - 1];
    for (int i = begin; i < end; i++) {
        int c = g_cnt[i];
        g_rowptr[i] = run;
        g_pos[i] = run;
        run += c;
    }
    if (t == T - 1) g_rowptr[NN] = run;
}
__global__ void scatter_kernel(const int* __restrict__ ei) {
    int i = blockIdx.x * blockDim.x + threadIdx.x;
    if (i >= EE) return;
    int d = ei[EE + i];
    int p = atomicAdd(&g_pos[d], 1);
    g_col[p] = ei[i];
}

// ---------------- BN stats for input x (slot 0) ------------------------------
__global__ void stats_in_kernel(const float* __restrict__ x) {
    int f = threadIdx.x % 4;
    int sub = threadIdx.x / 4;
    int r = blockIdx.x * 32 + sub;
    int step = gridDim.x * 32;
    float s = 0.f, q = 0.f;
    for (; r < NN; r += step) {
        float v = x[(size_t)r * 22 + f];
        s += v;
        q = fmaf(v, v, q);
    }
    int shard = blockIdx.x & 7;
    atomicAdd(&g_stats[shard * 256 + f], (double)s);
    atomicAdd(&g_stats[shard * 256 + 128 + f], (double)q);
}

// ---------------- logits via va vectors (layer 1) ----------------------------
template <int DIN, int C, bool RELU>
__global__ void valogits_kernel(const float* __restrict__ xin, int istride, int slot,
                                const float* __restrict__ W,
                                const float* __restrict__ as,
                                const float* __restrict__ ad,
                                const float* __restrict__ g,
                                const float* __restrict__ be) {
    constexpr int DOUT = 4 * C;
    const float* in = xin ? xin : g_out;
    __shared__ float vas[4][DIN], vad[4][DIN];
    __shared__ float sc[DIN], sb[DIN];
    int tid = threadIdx.x;
    for (int e = tid; e < 8 * DIN; e += 256) {
        int which = e / (4 * DIN);
        int rem = e % (4 * DIN);
        int h = rem / DIN, k = rem % DIN;
        const float* av = which ? ad : as;
        float sum = 0.f;
        for (int c = 0; c < C; c++)
            sum = fmaf(W[k * DOUT + h * C + c], av[h * C + c], sum);
        if (which) vad[h][k] = sum; else vas[h][k] = sum;
    }
    if (tid < DIN) bn_from_stats(tid, slot, g, be, sc, sb);
    __syncthreads();
    int n = blockIdx.x * 256 + tid;
    if (n >= NN) return;
    float accs[4] = {0.f, 0.f, 0.f, 0.f};
    float accd[4] = {0.f, 0.f, 0.f, 0.f};
    const float* row = in + (size_t)n * istride;
#pragma unroll 4
    for (int k = 0; k < DIN; k++) {
        float a = fmaf(row[k], sc[k], sb[k]);
        if (RELU) a = fmaxf(a, 0.f);
#pragma unroll
        for (int h = 0; h < 4; h++) {
            accs[h] = fmaf(a, vas[h][k], accs[h]);
            accd[h] = fmaf(a, vad[h][k], accd[h]);
        }
    }
    *(float4*)(g_als + n * 4) = make_float4(accs[0], accs[1], accs[2], accs[3]);
    *(float4*)(g_ald + n * 4) = make_float4(accd[0], accd[1], accd[2], accd[3]);
}

// ---------------- layer-1: persistent input-space agg + projection + stats ---
__global__ void __launch_bounds__(256) agg_in4_kernel(const float* __restrict__ x,
                                                      const float* __restrict__ W,
                                                      const float* __restrict__ g0,
                                                      const float* __restrict__ be0) {
    __shared__ float4 s_w[8][SCAP];
    __shared__ int    s_src[8][SCAP];
    __shared__ float  Ws[4 * 64];
    __shared__ float  scs[4], sbs[4];
    __shared__ float  s_sum[8][64], s_sq[8][64];
    int tid = threadIdx.x;
    for (int i = tid; i < 4 * 64; i += 256) Ws[i] = W[i];
    for (int i = tid; i < 8 * 64; i += 256) { ((float*)s_sum)[i] = 0.f; ((float*)s_sq)[i] = 0.f; }
    if (tid < 4) bn_from_stats(tid, 0, g0, be0, scs, sbs);
    __syncthreads();

    int wib = tid >> 5;
    int lane = tid & 31;
    int gw = blockIdx.x * 8 + wib;
    const int NW = gridDim.x * 8;
    float4 sc4 = make_float4(scs[0], scs[1], scs[2], scs[3]);
    float4 sb4 = make_float4(sbs[0], sbs[1], sbs[2], sbs[3]);
    int c0 = lane * 2;
    int h = lane >> 3;

    for (int n = gw; n < NN; n += NW) {
        int start = g_rowptr[n];
        int deg = g_rowptr[n + 1] - start;
        float4 ald4 = *(const float4*)(g_ald + n * 4);

        float4 s4;
        bool fits = weight_stage(n, start, deg, ald4, lane,
                                 &s_w[wib][0], &s_src[wib][0], s4);

        float4 acc0 = make_float4(0.f,0.f,0.f,0.f), acc1 = acc0, acc2 = acc0, acc3 = acc0;
        if (fits) {
#pragma unroll 2
            for (int i = lane; i <= deg; i += 32) {
                int s = s_src[wib][i];
                float4 w4 = s_w[wib][i];
                const float* p = x + (size_t)s * 22;
                float2 u0 = *(const float2*)p;
                float2 u1 = *(const float2*)(p + 2);
                float4 v = make_float4(fmaf(u0.x, sc4.x, sb4.x), fmaf(u0.y, sc4.y, sb4.y),
                                       fmaf(u1.x, sc4.z, sb4.z), fmaf(u1.y, sc4.w, sb4.w));
                acc0.x = fmaf(v.x, w4.x, acc0.x); acc0.y = fmaf(v.y, w4.x, acc0.y);
                acc0.z = fmaf(v.z, w4.x, acc0.z); acc0.w = fmaf(v.w, w4.x, acc0.w);
                acc1.x = fmaf(v.x, w4.y, acc1.x); acc1.y = fmaf(v.y, w4.y, acc1.y);
                acc1.z = fmaf(v.z, w4.y, acc1.z); acc1.w = fmaf(v.w, w4.y, acc1.w);
                acc2.x = fmaf(v.x, w4.z, acc2.x); acc2.y = fmaf(v.y, w4.z, acc2.y);
                acc2.z = fmaf(v.z, w4.z, acc2.z); acc2.w = fmaf(v.w, w4.z, acc2.w);
                acc3.x = fmaf(v.x, w4.w, acc3.x); acc3.y = fmaf(v.y, w4.w, acc3.y);
                acc3.z = fmaf(v.z, w4.w, acc3.z); acc3.w = fmaf(v.w, w4.w, acc3.w);
            }
        } else {
            for (int i = lane; i <= deg; i += 32) {
                int s = (i < deg) ? g_col[start + i] : n;
                float4 a = *(const float4*)(g_als + (size_t)s * 4);
                float4 e = lrelu4add(a, ald4);
                float4 w4 = make_float4(__expf(e.x), __expf(e.y), __expf(e.z), __expf(e.w));
                const float* p = x + (size_t)s * 22;
                float2 u0 = *(const float2*)p;
                float2 u1 = *(const float2*)(p + 2);
                float4 v = make_float4(fmaf(u0.x, sc4.x, sb4.x), fmaf(u0.y, sc4.y, sb4.y),
                                       fmaf(u1.x, sc4.z, sb4.z), fmaf(u1.y, sc4.w, sb4.w));
                acc0.x = fmaf(v.x, w4.x, acc0.x); acc0.y = fmaf(v.y, w4.x, acc0.y);
                acc0.z = fmaf(v.z, w4.x, acc0.z); acc0.w = fmaf(v.w, w4.x, acc0.w);
                acc1.x = fmaf(v.x, w4.y, acc1.x); acc1.y = fmaf(v.y, w4.y, acc1.y);
                acc1.z = fmaf(v.z, w4.y, acc1.z); acc1.w = fmaf(v.w, w4.y, acc1.w);
                acc2.x = fmaf(v.x, w4.z, acc2.x); acc2.y = fmaf(v.y, w4.z, acc2.y);
                acc2.z = fmaf(v.z, w4.z, acc2.z); acc2.w = fmaf(v.w, w4.z, acc2.w);
                acc3.x = fmaf(v.x, w4.w, acc3.x); acc3.y = fmaf(v.y, w4.w, acc3.y);
                acc3.z = fmaf(v.z, w4.w, acc3.z); acc3.w = fmaf(v.w, w4.w, acc3.w);
            }
        }
        warpSum4(acc0); warpSum4(acc1); warpSum4(acc2); warpSum4(acc3);
        float4 inv = make_float4(1.f / (s4.x + 1e-16f), 1.f / (s4.y + 1e-16f),
                                 1.f / (s4.z + 1e-16f), 1.f / (s4.w + 1e-16f));
        acc0.x *= inv.x; acc0.y *= inv.x; acc0.z *= inv.x; acc0.w *= inv.x;
        acc1.x *= inv.y; acc1.y *= inv.y; acc1.z *= inv.y; acc1.w *= inv.y;
        acc2.x *= inv.z; acc2.y *= inv.z; acc2.z *= inv.z; acc2.w *= inv.z;
        acc3.x *= inv.w; acc3.y *= inv.w; acc3.z *= inv.w; acc3.w *= inv.w;

        float4 ah = (h == 0) ? acc0 : (h == 1) ? acc1 : (h == 2) ? acc2 : acc3;
        float o0 = ah.x * Ws[0 * 64 + c0] + ah.y * Ws[1 * 64 + c0]
                 + ah.z * Ws[2 * 64 + c0] + ah.w * Ws[3 * 64 + c0];
        float o1 = ah.x * Ws[0 * 64 + c0 + 1] + ah.y * Ws[1 * 64 + c0 + 1]
                 + ah.z * Ws[2 * 64 + c0 + 1] + ah.w * Ws[3 * 64 + c0 + 1];
        *(float2*)(g_out + (size_t)n * 64 + c0) = make_float2(o0, o1);
        // fused stats (lane owns channels c0, c0+1; no contention within warp)
        s_sum[wib][c0]     += o0;  s_sq[wib][c0]     += o0 * o0;
        s_sum[wib][c0 + 1] += o1;  s_sq[wib][c0 + 1] += o1 * o1;
        __syncwarp();
    }
    __syncthreads();
    int shard = blockIdx.x & 7;
    for (int i = tid; i < 64; i += 256) {
        float su = 0.f, qq = 0.f;
#pragma unroll
        for (int w2 = 0; w2 < 8; w2++) { su += s_sum[w2][i]; qq += s_sq[w2][i]; }
        atomicAdd(&g_stats[1 * 2048 + shard * 256 + i], (double)su);
        atomicAdd(&g_stats[1 * 2048 + shard * 256 + 128 + i], (double)qq);
    }
}

// ---------------- GEMM + attention-logit epilogue (2 rows/thread, fp16 h) ----
template <int DIN, int DOUT, bool RELU>
__global__ void __launch_bounds__(256) gemm_kernel(
                            const float* __restrict__ Wg,
                            const float* __restrict__ asg,
                            const float* __restrict__ adg,
                            const float* __restrict__ g,
                            const float* __restrict__ be,
                            int slot) {
    const float* in = g_out;
    constexpr int R = DOUT / 32;
    constexpr int ROWS = 2 * (256 / R);
    constexpr int C = DOUT / 4;
    constexpr int HPT = 32 / C;
    __shared__ __align__(16) float Ws[DIN * DOUT];
    __shared__ float as_sh[DOUT], ad_sh[DOUT];
    __shared__ float sc_sh[DIN], sb_sh[DIN];
    int tid = threadIdx.x;
    for (int i = tid; i < DIN * DOUT; i += 256) Ws[i] = Wg[i];
    if (tid < DOUT) { as_sh[tid] = asg[tid]; ad_sh[tid] = adg[tid]; }
    if (tid < DIN)  bn_from_stats(tid, slot, g, be, sc_sh, sb_sh);
    __syncthreads();
    int r0 = blockIdx.x * ROWS + 2 * (tid / R);
    int cg = tid % R;
    if (r0 >= NN) return;
    bool has1 = (r0 + 1 < NN);
    int r1 = has1 ? (r0 + 1) : r0;

    float acc0[32], acc1[32];
#pragma unroll
    for (int j = 0; j < 32; j++) { acc0[j] = 0.f; acc1[j] = 0.f; }
    const float* i0 = in + (size_t)r0 * DIN;
    const float* i1 = in + (size_t)r1 * DIN;
    const float* wp = Ws + cg * 32;
#pragma unroll 2
    for (int k = 0; k < DIN; k++) {
        float a0 = fmaf(i0[k], sc_sh[k], sb_sh[k]);
        float a1 = fmaf(i1[k], sc_sh[k], sb_sh[k]);
        if (RELU) { a0 = fmaxf(a0, 0.f); a1 = fmaxf(a1, 0.f); }
        const float4* wv = (const float4*)(wp + k * DOUT);
#pragma unroll
        for (int j4 = 0; j4 < 8; j4++) {
            float4 w = wv[j4];
            acc0[4*j4+0] = fmaf(a0, w.x, acc0[4*j4+0]);
            acc0[4*j4+1] = fmaf(a0, w.y, acc0[4*j4+1]);
            acc0[4*j4+2] = fmaf(a0, w.z, acc0[4*j4+2]);
            acc0[4*j4+3] = fmaf(a0, w.w, acc0[4*j4+3]);
            acc1[4*j4+0] = fmaf(a1, w.x, acc1[4*j4+0]);
            acc1[4*j4+1] = fmaf(a1, w.y, acc1[4*j4+1]);
            acc1[4*j4+2] = fmaf(a1, w.z, acc1[4*j4+2]);
            acc1[4*j4+3] = fmaf(a1, w.w, acc1[4*j4+3]);
        }
    }
    {
        uint4* hp0 = (uint4*)((__half*)g_h16 + (size_t)r0 * DOUT + cg * 32);
#pragma unroll
        for (int q = 0; q < 4; q++) {
            uint4 u;
            u.x = f2h2(acc0[8*q+0], acc0[8*q+1]);
            u.y = f2h2(acc0[8*q+2], acc0[8*q+3]);
            u.z = f2h2(acc0[8*q+4], acc0[8*q+5]);
            u.w = f2h2(acc0[8*q+6], acc0[8*q+7]);
            hp0[q] = u;
        }
        if (has1) {
            uint4* hp1 = (uint4*)((__half*)g_h16 + (size_t)r1 * DOUT + cg * 32);
#pragma unroll
            for (int q = 0; q < 4; q++) {
                uint4 u;
                u.x = f2h2(acc1[8*q+0], acc1[8*q+1]);
                u.y = f2h2(acc1[8*q+2], acc1[8*q+3]);
                u.z = f2h2(acc1[8*q+4], acc1[8*q+5]);
                u.w = f2h2(acc1[8*q+6], acc1[8*q+7]);
                hp1[q] = u;
            }
        }
    }
#pragma unroll
    for (int u = 0; u < HPT; u++) {
        float ss0 = 0.f, dd0 = 0.f, ss1 = 0.f, dd1 = 0.f;
#pragma unroll
        for (int j = 0; j < C; j++) {
            float aw = as_sh[cg * 32 + u * C + j];
            float dw = ad_sh[cg * 32 + u * C + j];
            ss0 = fmaf(acc0[u * C + j], aw, ss0);
            dd0 = fmaf(acc0[u * C + j], dw, dd0);
            ss1 = fmaf(acc1[u * C + j], aw, ss1);
            dd1 = fmaf(acc1[u * C + j], dw, dd1);
        }
        int head = (cg * 32) / C + u;
        g_als[r0 * 4 + head] = ss0;
        g_ald[r0 * 4 + head] = dd0;
        if (has1) {
            g_als[r1 * 4 + head] = ss1;
            g_ald[r1 * 4 + head] = dd1;
        }
    }
}

// ---------------- persistent softmax+aggregation + fused stats ---------------
template <int DOUT, int VPT>
__global__ void __launch_bounds__(256) agg_node_kernel(int slot) {
    constexpr int C   = DOUT / 4;
    constexpr int LPE = DOUT / VPT;
    constexpr int EPW = 32 / LPE;
    constexpr int NV  = VPT / 8;
    static_assert(VPT <= C, "lane channels must stay within one head");
    static_assert(VPT >= 8, "need at least one uint4 per lane");
    __shared__ float4 s_w[8][SCAP];
    __shared__ int    s_src[8][SCAP];
    __shared__ float  s_sum[8][DOUT], s_sq[8][DOUT];
    int tid = threadIdx.x;
    int wib = tid >> 5;
    int lane = tid & 31;
    for (int i = tid; i < 8 * DOUT; i += 256) { ((float*)s_sum)[i] = 0.f; ((float*)s_sq)[i] = 0.f; }
    __syncthreads();

    int cl = lane % LPE;
    int sg = lane / LPE;
    int head = (cl * VPT) / C;
    int gw = blockIdx.x * 8 + wib;
    const int NW = gridDim.x * 8;

    for (int n = gw; n < NN; n += NW) {
        int start = g_rowptr[n];
        int deg = g_rowptr[n + 1] - start;
        float4 ald4 = *(const float4*)(g_ald + n * 4);

        float4 s4;
        bool fits = weight_stage(n, start, deg, ald4, lane,
                                 &s_w[wib][0], &s_src[wib][0], s4);

        float sh = (head == 0) ? s4.x : (head == 1) ? s4.y : (head == 2) ? s4.z : s4.w;
        float invh = 1.f / (sh + 1e-16f);

        float4 accA[NV], accB[NV];
#pragma unroll
        for (int v = 0; v < NV; v++) {
            accA[v] = make_float4(0.f, 0.f, 0.f, 0.f);
            accB[v] = make_float4(0.f, 0.f, 0.f, 0.f);
        }

        if (fits) {
            const float* swf = (const float*)&s_w[wib][0];
#pragma unroll 4
            for (int i = sg; i <= deg; i += EPW) {
                int s = s_src[wib][i];
                float w = swf[i * 4 + head];
                const uint4* hp = (const uint4*)((const __half*)g_h16 + (size_t)s * DOUT + cl * VPT);
#pragma unroll
                for (int v = 0; v < NV; v++) {
                    uint4 u = hp[v];
                    float2 f0 = h2f2(u.x), f1 = h2f2(u.y), f2 = h2f2(u.z), f3 = h2f2(u.w);
                    accA[v].x = fmaf(f0.x, w, accA[v].x); accA[v].y = fmaf(f0.y, w, accA[v].y);
                    accA[v].z = fmaf(f1.x, w, accA[v].z); accA[v].w = fmaf(f1.y, w, accA[v].w);
                    accB[v].x = fmaf(f2.x, w, accB[v].x); accB[v].y = fmaf(f2.y, w, accB[v].y);
                    accB[v].z = fmaf(f3.x, w, accB[v].z); accB[v].w = fmaf(f3.y, w, accB[v].w);
                }
            }
        } else {
            float aldh = (head == 0) ? ald4.x : (head == 1) ? ald4.y : (head == 2) ? ald4.z : ald4.w;
            for (int i = sg; i <= deg; i += EPW) {
                int s = (i < deg) ? g_col[start + i] : n;
                float av = __ldg(&g_als[s * 4 + head]);
                float w = __expf(lrelu(av + aldh));
                const uint4* hp = (const uint4*)((const __half*)g_h16 + (size_t)s * DOUT + cl * VPT);
#pragma unroll
                for (int v = 0; v < NV; v++) {
                    uint4 u = hp[v];
                    float2 f0 = h2f2(u.x), f1 = h2f2(u.y), f2 = h2f2(u.z), f3 = h2f2(u.w);
                    accA[v].x = fmaf(f0.x, w, accA[v].x); accA[v].y = fmaf(f0.y, w, accA[v].y);
                    accA[v].z = fmaf(f1.x, w, accA[v].z); accA[v].w = fmaf(f1.y, w, accA[v].w);
                    accB[v].x = fmaf(f2.x, w, accB[v].x); accB[v].y = fmaf(f2.y, w, accB[v].y);
                    accB[v].z = fmaf(f3.x, w, accB[v].z); accB[v].w = fmaf(f3.y, w, accB[v].w);
                }
            }
        }
#pragma unroll
        for (int off = LPE; off < 32; off <<= 1) {
#pragma unroll
            for (int v = 0; v < NV; v++) {
                accA[v].x += __shfl_xor_sync(0xffffffffu, accA[v].x, off);
                accA[v].y += __shfl_xor_sync(0xffffffffu, accA[v].y, off);
                accA[v].z += __shfl_xor_sync(0xffffffffu, accA[v].z, off);
                accA[v].w += __shfl_xor_sync(0xffffffffu, accA[v].w, off);
                accB[v].x += __shfl_xor_sync(0xffffffffu, accB[v].x, off);
                accB[v].y += __shfl_xor_sync(0xffffffffu, accB[v].y, off);
                accB[v].z += __shfl_xor_sync(0xffffffffu, accB[v].z, off);
                accB[v].w += __shfl_xor_sync(0xffffffffu, accB[v].w, off);
            }
        }
        if (sg == 0) {
            float4* op = (float4*)(g_out + (size_t)n * DOUT + cl * VPT);
#pragma unroll
            for (int v = 0; v < NV; v++) {
                accA[v].x *= invh; accA[v].y *= invh; accA[v].z *= invh; accA[v].w *= invh;
                accB[v].x *= invh; accB[v].y *= invh; accB[v].z *= invh; accB[v].w *= invh;
                op[2 * v + 0] = accA[v];
                op[2 * v + 1] = accB[v];
                int cb = cl * VPT + v * 8;
                s_sum[wib][cb+0] += accA[v].x; s_sq[wib][cb+0] += accA[v].x * accA[v].x;
                s_sum[wib][cb+1] += accA[v].y; s_sq[wib][cb+1] += accA[v].y * accA[v].y;
                s_sum[wib][cb+2] += accA[v].z; s_sq[wib][cb+2] += accA[v].z * accA[v].z;
                s_sum[wib][cb+3] += accA[v].w; s_sq[wib][cb+3] += accA[v].w * accA[v].w;
                s_sum[wib][cb+4] += accB[v].x; s_sq[wib][cb+4] += accB[v].x * accB[v].x;
                s_sum[wib][cb+5] += accB[v].y; s_sq[wib][cb+5] += accB[v].y * accB[v].y;
                s_sum[wib][cb+6] += accB[v].z; s_sq[wib][cb+6] += accB[v].z * accB[v].z;
                s_sum[wib][cb+7] += accB[v].w; s_sq[wib][cb+7] += accB[v].w * accB[v].w;
            }
        }
        __syncwarp();
    }
    __syncthreads();
    int shard = blockIdx.x & 7;
    for (int i = tid; i < DOUT; i += 256) {
        float su = 0.f, qq = 0.f;
#pragma unroll
        for (int w2 = 0; w2 < 8; w2++) { su += s_sum[w2][i]; qq += s_sq[w2][i]; }
        atomicAdd(&g_stats[slot * 2048 + shard * 256 + i], (double)su);
        atomicAdd(&g_stats[slot * 2048 + shard * 256 + 128 + i], (double)qq);
    }
}

// ---------------- final: bn+relu+linear(32->1) -------------------------------
__global__ void final_kernel(const float* __restrict__ ow, const float* __restrict__ ob,
                             const float* __restrict__ g, const float* __restrict__ be,
                             float* __restrict__ out) {
    __shared__ float sc[32], sb[32];
    if (threadIdx.x < 32) bn_from_stats(threadIdx.x, 4, g, be, sc, sb);
    __syncthreads();
    int n = blockIdx.x * blockDim.x + threadIdx.x;
    if (n >= NN) return;
    float acc = ob[0];
    const float4* row = (const float4*)(g_out + (size_t)n * 32);
#pragma unroll
    for (int q = 0; q < 8; q++) {
        float4 v = row[q];
        int k = 4 * q;
        float v0 = fmaxf(fmaf(v.x, sc[k + 0], sb[k + 0]), 0.f);
        float v1 = fmaxf(fmaf(v.y, sc[k + 1], sb[k + 1]), 0.f);
        float v2 = fmaxf(fmaf(v.z, sc[k + 2], sb[k + 2]), 0.f);
        float v3 = fmaxf(fmaf(v.w, sc[k + 3], sb[k + 3]), 0.f);
        acc = fmaf(v0, ow[k + 0], acc);
        acc = fmaf(v1, ow[k + 1], acc);
        acc = fmaf(v2, ow[k + 2], acc);
        acc = fmaf(v3, ow[k + 3], acc);
    }
    out[n] = acc;
}

// ---------------- launch ------------------------------------------------------
extern "C" void kernel_launch(void* const* d_in, const int* in_sizes, int n_in,
                              void* d_out, int out_size) {
    bool layB = (in_sizes[1] == 2 * EE);
    const float* x = (const float*)d_in[0];
    const int* ei = (const int*)d_in[layB ? 1 : (n_in - 1)];
    int base = layB ? 2 : 1;
    const float *W[4], *As[4], *Ad[4], *G[4], *Be[4];
    for (int l = 0; l < 4; l++) {
        int b = base + 6 * l;
        W[l]  = (const float*)d_in[b];
        As[l] = (const float*)d_in[b + 1];
        Ad[l] = (const float*)d_in[b + 2];
        G[l]  = (const float*)d_in[b + 4];
        Be[l] = (const float*)d_in[b + 5];
    }
    int tb = base + 24;
    const float* g0  = (const float*)d_in[tb];
    const float* be0 = (const float*)d_in[tb + 1];
    const float* ow  = (const float*)d_in[tb + 2];
    const float* ob  = (const float*)d_in[tb + 3];
    float* out = (float*)d_out;

    const int TPB = 256;
    int egrid = (EE + TPB - 1) / TPB;

    // CSR build + stats-slot zero
    zero_cnt_kernel<<<(NN + TPB - 1) / TPB, TPB>>>();
    hist_kernel<<<egrid, TPB>>>(ei);
    scan_kernel<<<1, 1024>>>();
    scatter_kernel<<<egrid, TPB>>>(ei);

    // input BN stats (x[:, :4], stride 22) -> slot 0
    stats_in_kernel<<<1024, 128>>>(x);

    // layer 1: 4 -> 64 (persistent input-space agg + projection + stats slot 1)
    valogits_kernel<4, 16, false><<<(NN + 255) / 256, 256>>>(x, 22, 0, W[0], As[0], Ad[0], g0, be0);
    agg_in4_kernel<<<PBLK, TPB>>>(x, W[0], g0, be0);

    // layer 2: 64 -> 128 (agg writes stats slot 2)
    gemm_kernel<64, 128, true><<<(NN + 127) / 128, 256>>>(W[1], As[1], Ad[1], G[0], Be[0], 1);
    agg_node_kernel<128, 16><<<PBLK, TPB>>>(2);

    // layer 3: 128 -> 64 (agg writes stats slot 3)
    gemm_kernel<128, 64, true><<<(NN + 255) / 256, 256>>>(W[2], As[2], Ad[2], G[1], Be[1], 2);
    agg_node_kernel<64, 8><<<PBLK, TPB>>>(3);

    // layer 4: 64 -> 32 (agg writes stats slot 4)
    gemm_kernel<64, 32, true><<<(NN + 511) / 512, 256>>>(W[3], As[3], Ad[3], G[2], Be[2], 3);
    agg_node_kernel<32, 8><<<PBLK, TPB>>>(4);

    // output head (BN from slot 4)
    final_kernel<<<(NN + 255) / 256, 256>>>(ow, ob, G[3], Be[3], out);
}